// round 10
// baseline (speedup 1.0000x reference)
#include <cuda_runtime.h>
#include <cuda_fp16.h>
#include <math.h>
#include <stdint.h>

#define BSZ   2048
#define INSZ  512
#define HSZ   512
#define OUTSZ 256
#define NSZ   32768
#define H3    (3*HSZ)
#define T_MAX 48
#define BH    (BSZ*HSZ)

#define BM 128
#define BN 128
#define STAGE_BYTES_G (2*BM*128)
#define STAGES 3
#define SMEM_G (STAGES*STAGE_BYTES_G)       // 98304

#define NTILES 576
#define NBLK   288

__device__ float  d_h0fA[BH], d_h0fB[BH], d_h1fA[BH], d_h1fB[BH];
__device__ __half d_h0hA[BH], d_h0hB[BH], d_h1hA[BH], d_h1hB[BH];
__device__ float  d_A0[BSZ*H3];
__device__ float  d_G0[BSZ*H3];
__device__ float  d_G1[BSZ*H3];
__device__ float  d_A1[BSZ*H3];
__device__ __half d_Y1h[(size_t)T_MAX*BH];
__device__ __half d_xh   [BSZ*INSZ];
__device__ __half d_Wih0h[H3*INSZ];
__device__ __half d_Whh0h[H3*HSZ];
__device__ __half d_Wih1h[H3*HSZ];
__device__ __half d_Whh1h[H3*HSZ];
__device__ __half d_Wouth[OUTSZ*HSZ];
__device__ int    d_first[BSZ];
__device__ int    d_rowoff[NSZ];
__device__ int    d_T[1];
__device__ unsigned long long d_ctr;

__global__ void k_init_first(const int* __restrict__ psi) {
    int i = blockIdx.x * blockDim.x + threadIdx.x;
    if (i == 0) { d_T[0] = 0; d_ctr = 0ULL; }
    if (i < BH) {
        d_h0fA[i]=0.f; d_h0fB[i]=0.f; d_h1fA[i]=0.f; d_h1fB[i]=0.f;
        __half z = __float2half(0.f);
        d_h0hA[i]=z; d_h0hB[i]=z; d_h1hA[i]=z; d_h1hB[i]=z;
    }
    if (i < NSZ) {
        if (i == 0 || psi[i] != psi[i-1]) d_first[psi[i]] = i;
    }
}

__global__ void k_rank(const int* __restrict__ psi) {
    int j = blockIdx.x * blockDim.x + threadIdx.x;
    if (j >= NSZ) return;
    int v = psi[j];
    int r = j - d_first[v];
    d_rowoff[j] = r * BH + v * HSZ;
    atomicMax(&d_T[0], r + 1);
}

__device__ __forceinline__ void conv4(const float* src, __half* dst, int i) {
    float4 v = *(const float4*)(src + i);
    ((__half2*)(dst + i))[0] = __floats2half2_rn(v.x, v.y);
    ((__half2*)(dst + i))[1] = __floats2half2_rn(v.z, v.w);
}

__global__ void k_convAll(const float* __restrict__ x,  const float* __restrict__ wih0,
                          const float* __restrict__ whh0, const float* __restrict__ wih1,
                          const float* __restrict__ whh1, const float* __restrict__ wout) {
    int i = (blockIdx.x * blockDim.x + threadIdx.x) << 2;
    if (i < BSZ*INSZ)  conv4(x,    d_xh,    i);
    if (i < H3*INSZ)   conv4(wih0, d_Wih0h, i);
    if (i < H3*HSZ) {
        conv4(whh0, d_Whh0h, i);
        conv4(wih1, d_Wih1h, i);
        conv4(whh1, d_Whh1h, i);
    }
    if (i < OUTSZ*HSZ) conv4(wout, d_Wouth, i);
}

__device__ __forceinline__ void gemm_tile(
    const __half* __restrict__ A, const __half* __restrict__ W, float* __restrict__ C,
    int row0, int col0, int Nout, int K,
    const int* __restrict__ a_off, const float* __restrict__ bias,
    uint32_t smaddr, int tid)
{
    const int lane = tid & 31;
    const int warp = tid >> 5;
    const int wm   = warp >> 2;
    const int wn   = warp & 3;
    const int g    = lane >> 2;
    const int q    = lane & 3;

    const int lm   = tid >> 1;
    const int lkg0 = (tid & 1) * 4;

    long arow = a_off ? (long)a_off[row0 + lm] : (long)(row0 + lm) * K;
    const __half* agp = A + arow;
    const __half* wgp = W + (long)(col0 + lm) * K;

    uint32_t soffB[4];
#pragma unroll
    for (int j = 0; j < 4; j++)
        soffB[j] = (uint32_t)(lm * 128 + (((lkg0 + j) ^ (lm & 7)) << 4));

#define LOAD_STAGE_T(st, kt) do {                                            \
        uint32_t dA = smaddr + (st)*STAGE_BYTES_G;                           \
        uint32_t dW = dA + BM*128;                                           \
        const __half* ga = agp + (size_t)(kt)*64;                            \
        const __half* gw = wgp + (size_t)(kt)*64;                            \
        _Pragma("unroll")                                                    \
        for (int j = 0; j < 4; j++) {                                        \
            asm volatile("cp.async.cg.shared.global [%0], [%1], 16;"         \
                         :: "r"(dA + soffB[j]), "l"(ga + (lkg0 + j)*8));     \
            asm volatile("cp.async.cg.shared.global [%0], [%1], 16;"         \
                         :: "r"(dW + soffB[j]), "l"(gw + (lkg0 + j)*8));     \
        }                                                                    \
    } while (0)

    float acc[4][4][4];
#pragma unroll
    for (int a = 0; a < 4; a++)
#pragma unroll
        for (int b = 0; b < 4; b++)
#pragma unroll
            for (int c = 0; c < 4; c++) acc[a][b][c] = 0.f;

    const int KT = K / 64;

#pragma unroll
    for (int s = 0; s < STAGES-1; s++) {
        LOAD_STAGE_T(s, s);
        asm volatile("cp.async.commit_group;" ::: "memory");
    }

    const uint32_t a_row15 = lane & 15;
    const uint32_t a_hi    = lane >> 4;
    const uint32_t x7      = lane & 7;
    const uint32_t w_hi    = lane >> 3;

    uint32_t aRowOff[4], wRowOff[4];
#pragma unroll
    for (int mi = 0; mi < 4; mi++)
        aRowOff[mi] = (uint32_t)((wm*64 + mi*16 + a_row15) * 128);
#pragma unroll
    for (int ni = 0; ni < 4; ni++)
        wRowOff[ni] = (uint32_t)((BM*128) + (wn*32 + ni*8 + x7) * 128);

    for (int kt = 0; kt < KT; kt++) {
        asm volatile("cp.async.wait_group %0;" :: "n"(STAGES-2) : "memory");
        __syncthreads();
        int ktn = kt + STAGES - 1;
        if (ktn < KT) LOAD_STAGE_T(ktn % STAGES, ktn);
        asm volatile("cp.async.commit_group;" ::: "memory");

        const uint32_t sbase = smaddr + (kt % STAGES)*STAGE_BYTES_G;
#pragma unroll
        for (int kp = 0; kp < 2; kp++) {
            uint32_t wq[4][4];
            const uint32_t wsw = ((4*kp + w_hi) ^ x7) << 4;
#pragma unroll
            for (int ni = 0; ni < 4; ni++) {
                asm volatile("ldmatrix.sync.aligned.m8n8.x4.shared.b16 {%0,%1,%2,%3}, [%4];"
                    : "=r"(wq[ni][0]), "=r"(wq[ni][1]), "=r"(wq[ni][2]), "=r"(wq[ni][3])
                    : "r"(sbase + wRowOff[ni] + wsw));
            }
#pragma unroll
            for (int kk2 = 0; kk2 < 2; kk2++) {
                const int kk = 2*kp + kk2;
                const uint32_t asw = ((2*kk + a_hi) ^ x7) << 4;
                uint32_t af[4][4];
#pragma unroll
                for (int mi = 0; mi < 4; mi++) {
                    asm volatile("ldmatrix.sync.aligned.m8n8.x4.shared.b16 {%0,%1,%2,%3}, [%4];"
                        : "=r"(af[mi][0]), "=r"(af[mi][1]), "=r"(af[mi][2]), "=r"(af[mi][3])
                        : "r"(sbase + aRowOff[mi] + asw));
                }
#pragma unroll
                for (int mi = 0; mi < 4; mi++)
#pragma unroll
                    for (int ni = 0; ni < 4; ni++)
                        asm volatile(
                            "mma.sync.aligned.m16n8k16.row.col.f32.f16.f16.f32 "
                            "{%0,%1,%2,%3}, {%4,%5,%6,%7}, {%8,%9}, {%0,%1,%2,%3};"
                            : "+f"(acc[mi][ni][0]), "+f"(acc[mi][ni][1]),
                              "+f"(acc[mi][ni][2]), "+f"(acc[mi][ni][3])
                            : "r"(af[mi][0]), "r"(af[mi][1]), "r"(af[mi][2]), "r"(af[mi][3]),
                              "r"(wq[ni][2*kk2]), "r"(wq[ni][2*kk2+1]));
            }
        }
    }

#pragma unroll
    for (int mi = 0; mi < 4; mi++) {
        int r0 = row0 + wm*64 + mi*16 + g;
#pragma unroll
        for (int ni = 0; ni < 4; ni++) {
            int c = col0 + wn*32 + ni*8 + 2*q;
            float b0 = 0.f, b1 = 0.f;
            if (bias) { b0 = bias[c]; b1 = bias[c+1]; }
            *(float2*)(C + (size_t)r0     * Nout + c) = make_float2(acc[mi][ni][0]+b0, acc[mi][ni][1]+b1);
            *(float2*)(C + (size_t)(r0+8) * Nout + c) = make_float2(acc[mi][ni][2]+b0, acc[mi][ni][3]+b1);
        }
    }
#undef LOAD_STAGE_T
}

__global__ __launch_bounds__(256, 2)
void gemm1(const __half* __restrict__ A, const __half* __restrict__ W, float* __restrict__ C,
           int N, int K, const int* __restrict__ a_off, const float* __restrict__ bias)
{
    extern __shared__ uint32_t sm[];
    const uint32_t smaddr = (uint32_t)__cvta_generic_to_shared(sm);
    gemm_tile(A, W, C, blockIdx.y * BM, blockIdx.x * BN, N, K, a_off, bias,
              smaddr, threadIdx.x);
}

__device__ __forceinline__ float sigm(float x) { return 1.f / (1.f + __expf(-x)); }
__device__ __forceinline__ float tanh_fast(float x) { return 2.f / (1.f + __expf(-2.f*x)) - 1.f; }

__global__ __launch_bounds__(256, 2)
void step_fused(const __half* __restrict__ h0h_in, const __half* __restrict__ h1h_in,
                const float* __restrict__ h0f_in, const float* __restrict__ h1f_in,
                float* __restrict__ h0f_out, float* __restrict__ h1f_out,
                __half* __restrict__ h0h_out, __half* __restrict__ h1h_out,
                __half* __restrict__ yout,
                const float* __restrict__ bih0, const float* __restrict__ bhh0,
                const float* __restrict__ bih1, const float* __restrict__ bhh1,
                int k, unsigned long long target)
{
    extern __shared__ uint32_t sm[];
    const uint32_t smaddr = (uint32_t)__cvta_generic_to_shared(sm);
    const int tid = threadIdx.x;
    const int bid = blockIdx.x;

    const int T = d_T[0];
    const bool do0 = (k < T);
    const bool do1 = (k >= 1 && k - 1 < T);

    // ---- phase 1: two GEMM tiles per block ----
#pragma unroll
    for (int ti = 0; ti < 2; ti++) {
        int tile = bid + ti * NBLK;
        int z    = tile / 192;
        int rem  = tile - z * 192;
        int rowb = rem / 12;
        int colb = rem - rowb * 12;
        bool valid = (z == 0) ? do0 : do1;

        __syncthreads();
        if (!valid) continue;

        const __half* A = (z == 1) ? h1h_in : h0h_in;
        const __half* W = (z == 0) ? d_Whh0h : ((z == 1) ? d_Whh1h : d_Wih1h);
        float*        C = (z == 0) ? d_G0 : ((z == 1) ? d_G1 : d_A1);

        gemm_tile(A, W, C, rowb * BM, colb * BN, H3, HSZ, nullptr, nullptr, smaddr, tid);
    }

    // ---- arrive at global barrier ----
    __syncthreads();
    if (tid == 0) {
        __threadfence();
        atomicAdd(&d_ctr, 1ULL);
    }
    if (!do0 && !do1) return;   // uniform across grid

    if (tid == 0) {
        while (*(volatile unsigned long long*)&d_ctr < target) __nanosleep(128);
    }
    __syncthreads();
    __threadfence();

    // ---- phase 2: merged GRU pointwise ----
    const int NV = BH / 4;
    for (int idx = bid * 256 + tid; idx < 2 * NV; idx += NBLK * 256) {
        int layer = (idx >= NV);
        int e = idx - layer * NV;
        if (layer == 0 && !do0) continue;
        if (layer == 1 && !do1) continue;

        int i = e << 2;
        int b = i >> 9, j = i & (HSZ - 1);
        int base = b * H3 + j;

        const float* Xs = layer ? d_A1 : d_A0;
        const float* Gs = layer ? d_G1 : d_G0;
        const float* bi = layer ? bih1 : bih0;
        const float* bh = layer ? bhh1 : bhh0;
        const float* hin = layer ? h1f_in : h0f_in;
        float* hout     = layer ? h1f_out : h0f_out;
        __half* hhout   = layer ? h1h_out : h0h_out;

        float4 ar = *(const float4*)(Xs + base);
        float4 az = *(const float4*)(Xs + base + HSZ);
        float4 an = *(const float4*)(Xs + base + 2*HSZ);
        float4 gr = *(const float4*)(Gs + base);
        float4 gz = *(const float4*)(Gs + base + HSZ);
        float4 gn = *(const float4*)(Gs + base + 2*HSZ);
        float4 h  = *(const float4*)(hin + i);
        float4 bir = *(const float4*)(bi + j);
        float4 biz = *(const float4*)(bi + j + HSZ);
        float4 bin = *(const float4*)(bi + j + 2*HSZ);
        float4 bhr = *(const float4*)(bh + j);
        float4 bhz = *(const float4*)(bh + j + HSZ);
        float4 bhn = *(const float4*)(bh + j + 2*HSZ);

        float hn[4];
        const float* pxr=(const float*)&ar; const float* pxz=(const float*)&az; const float* pxn=(const float*)&an;
        const float* pgr=(const float*)&gr; const float* pgz=(const float*)&gz; const float* pgn=(const float*)&gn;
        const float* ph =(const float*)&h;
        const float* pir=(const float*)&bir; const float* piz=(const float*)&biz; const float* pin=(const float*)&bin;
        const float* phr=(const float*)&bhr; const float* phz=(const float*)&bhz; const float* phn=(const float*)&bhn;
#pragma unroll
        for (int t4 = 0; t4 < 4; t4++) {
            float r = sigm(pxr[t4]+pir[t4] + pgr[t4]+phr[t4]);
            float z = sigm(pxz[t4]+piz[t4] + pgz[t4]+phz[t4]);
            float n = tanh_fast(pxn[t4]+pin[t4] + r * (pgn[t4]+phn[t4]));
            hn[t4] = (1.f - z) * n + z * ph[t4];
        }

        *(float4*)(hout + i) = make_float4(hn[0], hn[1], hn[2], hn[3]);
        __half2 p0 = __floats2half2_rn(hn[0], hn[1]);
        __half2 p1 = __floats2half2_rn(hn[2], hn[3]);
        ((__half2*)(hhout + i))[0] = p0;
        ((__half2*)(hhout + i))[1] = p1;
        if (layer) {
            ((__half2*)(yout + i))[0] = p0;
            ((__half2*)(yout + i))[1] = p1;
        }
    }
}

extern "C" void kernel_launch(void* const* d_in, const int* in_sizes, int n_in,
                              void* d_out, int out_size)
{
    const float* x    = (const float*)d_in[0];
    const float* Wih0 = (const float*)d_in[1];
    const float* Whh0 = (const float*)d_in[2];
    const float* bih0 = (const float*)d_in[3];
    const float* bhh0 = (const float*)d_in[4];
    const float* Wih1 = (const float*)d_in[5];
    const float* Whh1 = (const float*)d_in[6];
    const float* bih1 = (const float*)d_in[7];
    const float* bhh1 = (const float*)d_in[8];
    const float* Wout = (const float*)d_in[9];
    const float* bout = (const float*)d_in[10];
    const int*   psi  = (const int*)d_in[11];
    float* out = (float*)d_out;

    cudaFuncSetAttribute(gemm1,      cudaFuncAttributeMaxDynamicSharedMemorySize, SMEM_G);
    cudaFuncSetAttribute(step_fused, cudaFuncAttributeMaxDynamicSharedMemorySize, SMEM_G);

    float *p_h0fA,*p_h0fB,*p_h1fA,*p_h1fB,*p_A0;
    __half *p_h0hA,*p_h0hB,*p_h1hA,*p_h1hB,*p_Y1h,*p_xh,*p_Wih0h,*p_Wouth;
    int *p_rowoff;
    cudaGetSymbolAddress((void**)&p_h0fA, d_h0fA);
    cudaGetSymbolAddress((void**)&p_h0fB, d_h0fB);
    cudaGetSymbolAddress((void**)&p_h1fA, d_h1fA);
    cudaGetSymbolAddress((void**)&p_h1fB, d_h1fB);
    cudaGetSymbolAddress((void**)&p_h0hA, d_h0hA);
    cudaGetSymbolAddress((void**)&p_h0hB, d_h0hB);
    cudaGetSymbolAddress((void**)&p_h1hA, d_h1hA);
    cudaGetSymbolAddress((void**)&p_h1hB, d_h1hB);
    cudaGetSymbolAddress((void**)&p_A0,   d_A0);
    cudaGetSymbolAddress((void**)&p_Y1h,  d_Y1h);
    cudaGetSymbolAddress((void**)&p_xh,   d_xh);
    cudaGetSymbolAddress((void**)&p_Wih0h,d_Wih0h);
    cudaGetSymbolAddress((void**)&p_Wouth,d_Wouth);
    cudaGetSymbolAddress((void**)&p_rowoff, d_rowoff);

    const int PWI = (BH + 255) / 256;

    // launches: 0=init, 1=rank, 2=convAll, 3=A0 GEMM (ncu capture target)
    k_init_first<<<PWI, 256>>>(psi);
    k_rank<<<(NSZ + 255) / 256, 256>>>(psi);
    k_convAll<<<(BSZ*INSZ/4 + 255)/256, 256>>>(x, Wih0, Whh0, Wih1, Whh1, Wout);
    gemm1<<<dim3(H3/BN, BSZ/BM), 256, SMEM_G>>>(p_xh, p_Wih0h, p_A0, H3, INSZ, nullptr, nullptr);

    float  *h0f_in = p_h0fA, *h0f_out = p_h0fB;
    float  *h1f_in = p_h1fA, *h1f_out = p_h1fB;
    __half *h0h_in = p_h0hA, *h0h_out = p_h0hB;
    __half *h1h_in = p_h1hA, *h1h_out = p_h1hB;

    for (int k = 0; k <= T_MAX; k++) {
        __half* yptr = p_Y1h + (size_t)(k > 0 ? k-1 : 0) * BH;
        unsigned long long target = (unsigned long long)(k + 1) * NBLK;
        step_fused<<<NBLK, 256, SMEM_G>>>(
            h0h_in, h1h_in, h0f_in, h1f_in,
            h0f_out, h1f_out, h0h_out, h1h_out, yptr,
            bih0, bhh0, bih1, bhh1, k, target);

        float* tf; __half* th;
        tf = h0f_in; h0f_in = h0f_out; h0f_out = tf;
        tf = h1f_in; h1f_in = h1f_out; h1f_out = tf;
        th = h0h_in; h0h_in = h0h_out; h0h_out = th;
        th = h1h_in; h1h_in = h1h_out; h1h_out = th;
    }

    gemm1<<<dim3(OUTSZ/BN, NSZ/BM), 256, SMEM_G>>>(p_Y1h, p_Wouth, out, OUTSZ, HSZ, p_rowoff, bout);

    (void)in_sizes; (void)n_in; (void)out_size;
}

// round 11
// speedup vs baseline: 1.0375x; 1.0375x over previous
#include <cuda_runtime.h>
#include <cuda_fp16.h>
#include <math.h>
#include <stdint.h>

#define BSZ   2048
#define INSZ  512
#define HSZ   512
#define OUTSZ 256
#define NSZ   32768
#define H3    (3*HSZ)
#define T_MAX 48
#define BH    (BSZ*HSZ)

// ---- GEMM tile: 256x128, 512 threads, 3-stage cp.async ----
#define BM 256
#define BN 128
#define A_STAGE (BM*128)                 // 32768 B
#define W_STAGE (BN*128)                 // 16384 B
#define STAGE_BYTES (A_STAGE+W_STAGE)    // 49152 B
#define STAGES 3
#define SMEM_G (STAGES*STAGE_BYTES)      // 147456 B
#define THREADS 512

// ---------------- device scratch ----------------
__device__ float  d_h0fA[BH], d_h0fB[BH], d_h1fA[BH], d_h1fB[BH];
__device__ __half d_h0hA[BH], d_h0hB[BH], d_h1hA[BH], d_h1hB[BH];
__device__ __half d_A0h[BSZ*H3];
__device__ __half d_G0h[BSZ*H3];
__device__ __half d_G1h[BSZ*H3];
__device__ __half d_A1h[BSZ*H3];
__device__ __half d_Y1h[(size_t)T_MAX*BH];
__device__ __half d_xh   [BSZ*INSZ];
__device__ __half d_Wih0h[H3*INSZ];
__device__ __half d_Whh0h[H3*HSZ];
__device__ __half d_Wih1h[H3*HSZ];
__device__ __half d_Whh1h[H3*HSZ];
__device__ __half d_Wouth[OUTSZ*HSZ];
__device__ int    d_first[BSZ];
__device__ int    d_rowoff[NSZ];
__device__ int    d_T[1];

// ---------------- setup kernels ----------------
__global__ void k_init_first(const int* __restrict__ psi) {
    int i = blockIdx.x * blockDim.x + threadIdx.x;
    if (i == 0) d_T[0] = 0;
    if (i < BH) {
        d_h0fA[i]=0.f; d_h0fB[i]=0.f; d_h1fA[i]=0.f; d_h1fB[i]=0.f;
        __half z = __float2half(0.f);
        d_h0hA[i]=z; d_h0hB[i]=z; d_h1hA[i]=z; d_h1hB[i]=z;
    }
    if (i < NSZ) {
        if (i == 0 || psi[i] != psi[i-1]) d_first[psi[i]] = i;
    }
}

__global__ void k_rank(const int* __restrict__ psi) {
    int j = blockIdx.x * blockDim.x + threadIdx.x;
    if (j >= NSZ) return;
    int v = psi[j];
    int r = j - d_first[v];
    d_rowoff[j] = r * BH + v * HSZ;
    atomicMax(&d_T[0], r + 1);
}

__device__ __forceinline__ void conv4(const float* src, __half* dst, int i) {
    float4 v = *(const float4*)(src + i);
    ((__half2*)(dst + i))[0] = __floats2half2_rn(v.x, v.y);
    ((__half2*)(dst + i))[1] = __floats2half2_rn(v.z, v.w);
}

__global__ void k_convAll(const float* __restrict__ x,  const float* __restrict__ wih0,
                          const float* __restrict__ whh0, const float* __restrict__ wih1,
                          const float* __restrict__ whh1, const float* __restrict__ wout) {
    int i = (blockIdx.x * blockDim.x + threadIdx.x) << 2;
    if (i < BSZ*INSZ)  conv4(x,    d_xh,    i);
    if (i < H3*INSZ)   conv4(wih0, d_Wih0h, i);
    if (i < H3*HSZ) {
        conv4(whh0, d_Whh0h, i);
        conv4(wih1, d_Wih1h, i);
        conv4(whh1, d_Whh1h, i);
    }
    if (i < OUTSZ*HSZ) conv4(wout, d_Wouth, i);
}

// ---------------- GEMM tile device function (256x128, 512 threads) ----------------
// Output: fp16 to Ch if non-null, else fp32 to Cf (+bias).
__device__ __forceinline__ void gemm_tile(
    const __half* __restrict__ A, const __half* __restrict__ W,
    __half* __restrict__ Ch, float* __restrict__ Cf,
    int row0, int col0, int Nout, int K,
    const int* __restrict__ a_off, const float* __restrict__ bias,
    uint32_t smaddr, int tid)
{
    const int lane = tid & 31;
    const int warp = tid >> 5;       // 0..15
    const int wm   = warp >> 2;      // 0..3 (64-row warp tiles)
    const int wn   = warp & 3;       // 0..3 (32-col warp tiles)
    const int g    = lane >> 2;
    const int q    = lane & 3;

    // A loader: thread -> row tid>>1 (0..255), 16B-groups (tid&1)*4 + {0..3}
    const int a_row = tid >> 1;
    const int a_g0  = (tid & 1) * 4;
    long arow = a_off ? (long)a_off[row0 + a_row] : (long)(row0 + a_row) * K;
    const __half* agp = A + arow;
    uint32_t aoffB[4];
#pragma unroll
    for (int j = 0; j < 4; j++)
        aoffB[j] = (uint32_t)(a_row * 128 + (((a_g0 + j) ^ (a_row & 7)) << 4));

    // W loader: thread -> row tid&127, groups (tid>>7)*2 + {0,1}
    const int w_row = tid & 127;
    const int w_g0  = (tid >> 7) * 2;
    const __half* wgp = W + (long)(col0 + w_row) * K;
    uint32_t woffB[2];
#pragma unroll
    for (int j = 0; j < 2; j++)
        woffB[j] = (uint32_t)(w_row * 128 + (((w_g0 + j) ^ (w_row & 7)) << 4));

#define LOAD_STAGE_T(st, kt) do {                                            \
        uint32_t dA = smaddr + (st)*STAGE_BYTES;                             \
        uint32_t dW = dA + A_STAGE;                                          \
        const __half* ga = agp + (size_t)(kt)*64;                            \
        const __half* gw = wgp + (size_t)(kt)*64;                            \
        _Pragma("unroll")                                                    \
        for (int j = 0; j < 4; j++)                                          \
            asm volatile("cp.async.cg.shared.global [%0], [%1], 16;"         \
                         :: "r"(dA + aoffB[j]), "l"(ga + (a_g0 + j)*8));     \
        _Pragma("unroll")                                                    \
        for (int j = 0; j < 2; j++)                                          \
            asm volatile("cp.async.cg.shared.global [%0], [%1], 16;"         \
                         :: "r"(dW + woffB[j]), "l"(gw + (w_g0 + j)*8));     \
    } while (0)

    float acc[4][4][4];
#pragma unroll
    for (int a = 0; a < 4; a++)
#pragma unroll
        for (int b = 0; b < 4; b++)
#pragma unroll
            for (int c = 0; c < 4; c++) acc[a][b][c] = 0.f;

    const int KT = K / 64;

#pragma unroll
    for (int s = 0; s < STAGES-1; s++) {
        LOAD_STAGE_T(s, s);
        asm volatile("cp.async.commit_group;" ::: "memory");
    }

    const uint32_t a_row15 = lane & 15;
    const uint32_t a_hi    = lane >> 4;
    const uint32_t x7      = lane & 7;
    const uint32_t w_hi    = lane >> 3;

    uint32_t aRowOff[4], wRowOff[4];
#pragma unroll
    for (int mi = 0; mi < 4; mi++)
        aRowOff[mi] = (uint32_t)((wm*64 + mi*16 + a_row15) * 128);
#pragma unroll
    for (int ni = 0; ni < 4; ni++)
        wRowOff[ni] = (uint32_t)(A_STAGE + (wn*32 + ni*8 + x7) * 128);

    for (int kt = 0; kt < KT; kt++) {
        asm volatile("cp.async.wait_group %0;" :: "n"(STAGES-2) : "memory");
        __syncthreads();
        int ktn = kt + STAGES - 1;
        if (ktn < KT) LOAD_STAGE_T(ktn % STAGES, ktn);
        asm volatile("cp.async.commit_group;" ::: "memory");

        const uint32_t sbase = smaddr + (kt % STAGES)*STAGE_BYTES;
#pragma unroll
        for (int kp = 0; kp < 2; kp++) {
            uint32_t wq[4][4];
            const uint32_t wsw = ((4*kp + w_hi) ^ x7) << 4;
#pragma unroll
            for (int ni = 0; ni < 4; ni++) {
                asm volatile("ldmatrix.sync.aligned.m8n8.x4.shared.b16 {%0,%1,%2,%3}, [%4];"
                    : "=r"(wq[ni][0]), "=r"(wq[ni][1]), "=r"(wq[ni][2]), "=r"(wq[ni][3])
                    : "r"(sbase + wRowOff[ni] + wsw));
            }
#pragma unroll
            for (int kk2 = 0; kk2 < 2; kk2++) {
                const int kk = 2*kp + kk2;
                const uint32_t asw = ((2*kk + a_hi) ^ x7) << 4;
                uint32_t af[4][4];
#pragma unroll
                for (int mi = 0; mi < 4; mi++) {
                    asm volatile("ldmatrix.sync.aligned.m8n8.x4.shared.b16 {%0,%1,%2,%3}, [%4];"
                        : "=r"(af[mi][0]), "=r"(af[mi][1]), "=r"(af[mi][2]), "=r"(af[mi][3])
                        : "r"(sbase + aRowOff[mi] + asw));
                }
#pragma unroll
                for (int mi = 0; mi < 4; mi++)
#pragma unroll
                    for (int ni = 0; ni < 4; ni++)
                        asm volatile(
                            "mma.sync.aligned.m16n8k16.row.col.f32.f16.f16.f32 "
                            "{%0,%1,%2,%3}, {%4,%5,%6,%7}, {%8,%9}, {%0,%1,%2,%3};"
                            : "+f"(acc[mi][ni][0]), "+f"(acc[mi][ni][1]),
                              "+f"(acc[mi][ni][2]), "+f"(acc[mi][ni][3])
                            : "r"(af[mi][0]), "r"(af[mi][1]), "r"(af[mi][2]), "r"(af[mi][3]),
                              "r"(wq[ni][2*kk2]), "r"(wq[ni][2*kk2+1]));
            }
        }
    }

    if (Ch) {
#pragma unroll
        for (int mi = 0; mi < 4; mi++) {
            int r0 = row0 + wm*64 + mi*16 + g;
#pragma unroll
            for (int ni = 0; ni < 4; ni++) {
                int c = col0 + wn*32 + ni*8 + 2*q;
                *(__half2*)(Ch + (size_t)r0     * Nout + c) = __floats2half2_rn(acc[mi][ni][0], acc[mi][ni][1]);
                *(__half2*)(Ch + (size_t)(r0+8) * Nout + c) = __floats2half2_rn(acc[mi][ni][2], acc[mi][ni][3]);
            }
        }
    } else {
#pragma unroll
        for (int mi = 0; mi < 4; mi++) {
            int r0 = row0 + wm*64 + mi*16 + g;
#pragma unroll
            for (int ni = 0; ni < 4; ni++) {
                int c = col0 + wn*32 + ni*8 + 2*q;
                float b0 = 0.f, b1 = 0.f;
                if (bias) { b0 = bias[c]; b1 = bias[c+1]; }
                *(float2*)(Cf + (size_t)r0     * Nout + c) = make_float2(acc[mi][ni][0]+b0, acc[mi][ni][1]+b1);
                *(float2*)(Cf + (size_t)(r0+8) * Nout + c) = make_float2(acc[mi][ni][2]+b0, acc[mi][ni][3]+b1);
            }
        }
    }
#undef LOAD_STAGE_T
}

// single GEMM (A0 fp16-out; gather fp32-out)
__global__ __launch_bounds__(THREADS, 1)
void gemm_s(const __half* __restrict__ A, const __half* __restrict__ W,
            __half* __restrict__ Ch, float* __restrict__ Cf,
            int N, int K, const int* __restrict__ a_off, const float* __restrict__ bias)
{
    extern __shared__ uint32_t sm[];
    const uint32_t smaddr = (uint32_t)__cvta_generic_to_shared(sm);
    gemm_tile(A, W, Ch, Cf, blockIdx.y * BM, blockIdx.x * BN, N, K, a_off, bias,
              smaddr, threadIdx.x);
}

// wavefront GEMM: 3 operand sets via blockIdx.z, fp16 out, predicated on d_T
__global__ __launch_bounds__(THREADS, 1)
void gemm_w(const __half* __restrict__ h0h, const __half* __restrict__ h1h,
            int t0, int t1)
{
    {
        int tt = (blockIdx.z == 0) ? t0 : t1;
        if (tt < 0 || tt >= d_T[0]) return;
    }
    const __half* A = (blockIdx.z == 1) ? h1h : h0h;
    const __half* W = (blockIdx.z == 0) ? d_Whh0h : ((blockIdx.z == 1) ? d_Whh1h : d_Wih1h);
    __half*       C = (blockIdx.z == 0) ? d_G0h : ((blockIdx.z == 1) ? d_G1h : d_A1h);

    extern __shared__ uint32_t sm[];
    const uint32_t smaddr = (uint32_t)__cvta_generic_to_shared(sm);
    gemm_tile(A, W, C, nullptr, blockIdx.y * BM, blockIdx.x * BN, H3, HSZ,
              nullptr, nullptr, smaddr, threadIdx.x);
}

// ---------------- merged GRU pointwise (fp16 gates) ----------------
__device__ __forceinline__ float sigm(float x) { return 1.f / (1.f + __expf(-x)); }
__device__ __forceinline__ float tanh_fast(float x) { return 2.f / (1.f + __expf(-2.f*x)) - 1.f; }

__device__ __forceinline__ void ld4h(const __half* p, float* o) {
    __half2 v0 = *(const __half2*)(p);
    __half2 v1 = *(const __half2*)(p + 2);
    float2 f0 = __half22float2(v0);
    float2 f1 = __half22float2(v1);
    o[0] = f0.x; o[1] = f0.y; o[2] = f1.x; o[3] = f1.y;
}

__global__ void k_pw(const float* __restrict__ bih0, const float* __restrict__ bhh0,
                     const float* __restrict__ bih1, const float* __restrict__ bhh1,
                     const float* __restrict__ h0in, float* __restrict__ h0out,
                     __half* __restrict__ h0hout,
                     const float* __restrict__ h1in, float* __restrict__ h1out,
                     __half* __restrict__ h1hout, __half* __restrict__ yout, int k)
{
    const int T = d_T[0];
    int i4 = blockIdx.x * blockDim.x + threadIdx.x;
    if (i4 >= BH/4) return;
    int i = i4 << 2;
    int b = i >> 9, j = i & (HSZ-1);
    int base = b*H3 + j;

    const __half* Xs; const __half* Gs;
    const float* bi;  const float* bh;
    const float* hin; float* hout; __half* hhout;
    bool writeY;

    if (blockIdx.y == 0) {
        if (k >= T) return;
        Xs = d_A0h; Gs = d_G0h; bi = bih0; bh = bhh0;
        hin = h0in; hout = h0out; hhout = h0hout; writeY = false;
    } else {
        if (k < 1 || k-1 >= T) return;
        Xs = d_A1h; Gs = d_G1h; bi = bih1; bh = bhh1;
        hin = h1in; hout = h1out; hhout = h1hout; writeY = true;
    }

    float xr[4], xz[4], xn[4], gr[4], gz[4], gn[4];
    ld4h(Xs + base,         xr);
    ld4h(Xs + base + HSZ,   xz);
    ld4h(Xs + base + 2*HSZ, xn);
    ld4h(Gs + base,         gr);
    ld4h(Gs + base + HSZ,   gz);
    ld4h(Gs + base + 2*HSZ, gn);

    float4 h  = *(const float4*)(hin + i);
    float4 bir = *(const float4*)(bi + j);
    float4 biz = *(const float4*)(bi + j + HSZ);
    float4 bin = *(const float4*)(bi + j + 2*HSZ);
    float4 bhr = *(const float4*)(bh + j);
    float4 bhz = *(const float4*)(bh + j + HSZ);
    float4 bhn = *(const float4*)(bh + j + 2*HSZ);

    const float* ph =(const float*)&h;
    const float* pir=(const float*)&bir; const float* piz=(const float*)&biz; const float* pin=(const float*)&bin;
    const float* phr=(const float*)&bhr; const float* phz=(const float*)&bhz; const float* phn=(const float*)&bhn;

    float hn[4];
#pragma unroll
    for (int e = 0; e < 4; e++) {
        float r = sigm(xr[e]+pir[e] + gr[e]+phr[e]);
        float z = sigm(xz[e]+piz[e] + gz[e]+phz[e]);
        float n = tanh_fast(xn[e]+pin[e] + r * (gn[e]+phn[e]));
        hn[e] = (1.f - z) * n + z * ph[e];
    }

    *(float4*)(hout + i) = make_float4(hn[0], hn[1], hn[2], hn[3]);
    __half2 p0 = __floats2half2_rn(hn[0], hn[1]);
    __half2 p1 = __floats2half2_rn(hn[2], hn[3]);
    ((__half2*)(hhout + i))[0] = p0;
    ((__half2*)(hhout + i))[1] = p1;
    if (writeY) {
        ((__half2*)(yout + i))[0] = p0;
        ((__half2*)(yout + i))[1] = p1;
    }
}

// ---------------- host launch ----------------
extern "C" void kernel_launch(void* const* d_in, const int* in_sizes, int n_in,
                              void* d_out, int out_size)
{
    const float* x    = (const float*)d_in[0];
    const float* Wih0 = (const float*)d_in[1];
    const float* Whh0 = (const float*)d_in[2];
    const float* bih0 = (const float*)d_in[3];
    const float* bhh0 = (const float*)d_in[4];
    const float* Wih1 = (const float*)d_in[5];
    const float* Whh1 = (const float*)d_in[6];
    const float* bih1 = (const float*)d_in[7];
    const float* bhh1 = (const float*)d_in[8];
    const float* Wout = (const float*)d_in[9];
    const float* bout = (const float*)d_in[10];
    const int*   psi  = (const int*)d_in[11];
    float* out = (float*)d_out;

    cudaFuncSetAttribute(gemm_s, cudaFuncAttributeMaxDynamicSharedMemorySize, SMEM_G);
    cudaFuncSetAttribute(gemm_w, cudaFuncAttributeMaxDynamicSharedMemorySize, SMEM_G);

    float *p_h0fA,*p_h0fB,*p_h1fA,*p_h1fB;
    __half *p_h0hA,*p_h0hB,*p_h1hA,*p_h1hB,*p_A0h,*p_Y1h,*p_xh,*p_Wih0h,*p_Wouth;
    int *p_rowoff;
    cudaGetSymbolAddress((void**)&p_h0fA, d_h0fA);
    cudaGetSymbolAddress((void**)&p_h0fB, d_h0fB);
    cudaGetSymbolAddress((void**)&p_h1fA, d_h1fA);
    cudaGetSymbolAddress((void**)&p_h1fB, d_h1fB);
    cudaGetSymbolAddress((void**)&p_h0hA, d_h0hA);
    cudaGetSymbolAddress((void**)&p_h0hB, d_h0hB);
    cudaGetSymbolAddress((void**)&p_h1hA, d_h1hA);
    cudaGetSymbolAddress((void**)&p_h1hB, d_h1hB);
    cudaGetSymbolAddress((void**)&p_A0h,  d_A0h);
    cudaGetSymbolAddress((void**)&p_Y1h,  d_Y1h);
    cudaGetSymbolAddress((void**)&p_xh,   d_xh);
    cudaGetSymbolAddress((void**)&p_Wih0h,d_Wih0h);
    cudaGetSymbolAddress((void**)&p_Wouth,d_Wouth);
    cudaGetSymbolAddress((void**)&p_rowoff, d_rowoff);

    const int PWI = (BH + 255) / 256;
    const int PW4 = (BH/4 + 255) / 256;

    // launches: 0=init, 1=rank, 2=convAll, 3=A0 GEMM (ncu target)
    k_init_first<<<PWI, 256>>>(psi);
    k_rank<<<(NSZ + 255) / 256, 256>>>(psi);
    k_convAll<<<(BSZ*INSZ/4 + 255)/256, 256>>>(x, Wih0, Whh0, Wih1, Whh1, Wout);

    // A0 = x . Wih0^T (fp16 out; biases added in pw)
    gemm_s<<<dim3(H3/BN, BSZ/BM), THREADS, SMEM_G>>>(
        p_xh, p_Wih0h, p_A0h, nullptr, H3, INSZ, nullptr, nullptr);

    float  *h0f_in = p_h0fA, *h0f_out = p_h0fB;
    float  *h1f_in = p_h1fA, *h1f_out = p_h1fB;
    __half *h0h_in = p_h0hA, *h0h_out = p_h0hB;
    __half *h1h_in = p_h1hA, *h1h_out = p_h1hB;

    // wavefront: iteration k = layer0 step k + layer1 step k-1
    for (int k = 0; k <= T_MAX; k++) {
        gemm_w<<<dim3(H3/BN, BSZ/BM, 3), THREADS, SMEM_G>>>(h0h_in, h1h_in, k, k-1);

        __half* yptr = p_Y1h + (size_t)(k > 0 ? k-1 : 0) * BH;
        k_pw<<<dim3(PW4, 2), 256>>>(bih0, bhh0, bih1, bhh1,
                                    h0f_in, h0f_out, h0h_out,
                                    h1f_in, h1f_out, h1h_out, yptr, k);

        float* tf; __half* th;
        tf = h0f_in; h0f_in = h0f_out; h0f_out = tf;
        tf = h1f_in; h1f_in = h1f_out; h1f_out = tf;
        th = h0h_in; h0h_in = h0h_out; h0h_out = th;
        th = h1h_in; h1h_in = h1h_out; h1h_out = th;
    }

    // gathered output GEMM: out[N, OUT] = Y1h[rowoff[j]] . Wout^T + bout (fp32 out)
    gemm_s<<<dim3(OUTSZ/BN, NSZ/BM), THREADS, SMEM_G>>>(
        p_Y1h, p_Wouth, nullptr, out, OUTSZ, HSZ, p_rowoff, bout);

    (void)in_sizes; (void)n_in; (void)out_size;
}

// round 12
// speedup vs baseline: 1.4576x; 1.4049x over previous
#include <cuda_runtime.h>
#include <cuda_fp16.h>
#include <math.h>
#include <stdint.h>

#define BSZ   2048
#define INSZ  512
#define HSZ   512
#define OUTSZ 256
#define NSZ   32768
#define H3    (3*HSZ)
#define T_MAX 48
#define BH    (BSZ*HSZ)

#define BM 128
#define BN 128
#define STAGE_BYTES (2*BM*128)
#define STAGES 3
#define SMEM_G (STAGES*STAGE_BYTES)      // 98304

// ---------------- device scratch ----------------
__device__ float  d_h0fA[BH], d_h0fB[BH], d_h1fA[BH], d_h1fB[BH];
__device__ __half d_h0hA[BH], d_h0hB[BH], d_h1hA[BH], d_h1hB[BH];
__device__ __half d_A0h[BSZ*H3];
__device__ __half d_G0h[BSZ*H3];
__device__ __half d_G1h[BSZ*H3];
__device__ __half d_A1h[BSZ*H3];
__device__ __half d_Y1h[(size_t)T_MAX*BH];
__device__ __half d_xh   [BSZ*INSZ];
__device__ __half d_Wih0h[H3*INSZ];
__device__ __half d_Whh0h[H3*HSZ];
__device__ __half d_Wih1h[H3*HSZ];
__device__ __half d_Whh1h[H3*HSZ];
__device__ __half d_Wouth[OUTSZ*HSZ];
__device__ int    d_first[BSZ];
__device__ int    d_cnt[BSZ];
__device__ int    d_pos[BSZ];            // orig row -> permuted position
__device__ int    d_xoff[BSZ];           // permuted pos -> orig x row offset
__device__ int    d_rowoff[NSZ];
__device__ int    d_M[T_MAX+1];          // active rows at step t
__device__ int    d_T[1];

// ---------------- setup ----------------
__global__ void k_init_first(const int* __restrict__ psi) {
    int i = blockIdx.x * blockDim.x + threadIdx.x;
    if (i == 0) d_T[0] = 0;
    if (i < BSZ) d_cnt[i] = 0;
    if (i < BH) {
        d_h0fA[i]=0.f; d_h0fB[i]=0.f; d_h1fA[i]=0.f; d_h1fB[i]=0.f;
        __half z = __float2half(0.f);
        d_h0hA[i]=z; d_h0hB[i]=z; d_h1hA[i]=z; d_h1hB[i]=z;
    }
    if (i < NSZ) {
        if (i == 0 || psi[i] != psi[i-1]) d_first[psi[i]] = i;
    }
}

__global__ void k_count(const int* __restrict__ psi) {
    int j = blockIdx.x * blockDim.x + threadIdx.x;
    if (j < NSZ) atomicAdd(&d_cnt[psi[j]], 1);
}

// rank rows by (count desc, index asc); 8 blocks x 256 threads
__global__ void k_pos() {
    __shared__ int sc[BSZ];
    for (int j = threadIdx.x; j < BSZ; j += 256) sc[j] = d_cnt[j];
    __syncthreads();
    int i = blockIdx.x * 256 + threadIdx.x;
    int c = sc[i];
    int pos = 0;
    for (int j = 0; j < BSZ; j++) {
        int cj = sc[j];
        pos += (cj > c) || (cj == c && j < i);
    }
    d_pos[i] = pos;
    d_xoff[pos] = i * INSZ;
    atomicMax(&d_T[0], c);
}

// M(t) = #rows with cnt > t ; single block
__global__ void k_M() {
    __shared__ int sc[BSZ];
    for (int j = threadIdx.x; j < BSZ; j += 256) sc[j] = d_cnt[j];
    __syncthreads();
    int t = threadIdx.x;
    if (t <= T_MAX) {
        int m = 0;
        for (int j = 0; j < BSZ; j++) m += (sc[j] > t);
        d_M[t] = m;
    }
}

__global__ void k_rank(const int* __restrict__ psi) {
    int j = blockIdx.x * blockDim.x + threadIdx.x;
    if (j >= NSZ) return;
    int v = psi[j];
    int r = j - d_first[v];
    d_rowoff[j] = r * BH + d_pos[v] * HSZ;
}

__device__ __forceinline__ void conv4(const float* src, __half* dst, int i) {
    float4 v = *(const float4*)(src + i);
    ((__half2*)(dst + i))[0] = __floats2half2_rn(v.x, v.y);
    ((__half2*)(dst + i))[1] = __floats2half2_rn(v.z, v.w);
}

__global__ void k_convAll(const float* __restrict__ x,  const float* __restrict__ wih0,
                          const float* __restrict__ whh0, const float* __restrict__ wih1,
                          const float* __restrict__ whh1, const float* __restrict__ wout) {
    int i = (blockIdx.x * blockDim.x + threadIdx.x) << 2;
    if (i < BSZ*INSZ)  conv4(x,    d_xh,    i);
    if (i < H3*INSZ)   conv4(wih0, d_Wih0h, i);
    if (i < H3*HSZ) {
        conv4(whh0, d_Whh0h, i);
        conv4(wih1, d_Wih1h, i);
        conv4(whh1, d_Whh1h, i);
    }
    if (i < OUTSZ*HSZ) conv4(wout, d_Wouth, i);
}

// ---------------- GEMM tile (round-9 proven: 128x128, 256 thr, 3-stage) ----------------
__device__ __forceinline__ void gemm_tile(
    const __half* __restrict__ A, const __half* __restrict__ W,
    __half* __restrict__ Ch, float* __restrict__ Cf,
    int row0, int col0, int Nout, int K,
    const int* __restrict__ a_off, const float* __restrict__ bias,
    uint32_t smaddr, int tid)
{
    const int lane = tid & 31;
    const int warp = tid >> 5;
    const int wm   = warp >> 2;
    const int wn   = warp & 3;
    const int g    = lane >> 2;
    const int q    = lane & 3;

    const int lm   = tid >> 1;
    const int lkg0 = (tid & 1) * 4;

    long arow = a_off ? (long)a_off[row0 + lm] : (long)(row0 + lm) * K;
    const __half* agp = A + arow;
    const __half* wgp = W + (long)(col0 + lm) * K;

    uint32_t soffB[4];
#pragma unroll
    for (int j = 0; j < 4; j++)
        soffB[j] = (uint32_t)(lm * 128 + (((lkg0 + j) ^ (lm & 7)) << 4));

#define LOAD_STAGE_T(st, kt) do {                                            \
        uint32_t dA = smaddr + (st)*STAGE_BYTES;                             \
        uint32_t dW = dA + BM*128;                                           \
        const __half* ga = agp + (size_t)(kt)*64;                            \
        const __half* gw = wgp + (size_t)(kt)*64;                            \
        _Pragma("unroll")                                                    \
        for (int j = 0; j < 4; j++) {                                        \
            asm volatile("cp.async.cg.shared.global [%0], [%1], 16;"         \
                         :: "r"(dA + soffB[j]), "l"(ga + (lkg0 + j)*8));     \
            asm volatile("cp.async.cg.shared.global [%0], [%1], 16;"         \
                         :: "r"(dW + soffB[j]), "l"(gw + (lkg0 + j)*8));     \
        }                                                                    \
    } while (0)

    float acc[4][4][4];
#pragma unroll
    for (int a = 0; a < 4; a++)
#pragma unroll
        for (int b = 0; b < 4; b++)
#pragma unroll
            for (int c = 0; c < 4; c++) acc[a][b][c] = 0.f;

    const int KT = K / 64;

#pragma unroll
    for (int s = 0; s < STAGES-1; s++) {
        LOAD_STAGE_T(s, s);
        asm volatile("cp.async.commit_group;" ::: "memory");
    }

    const uint32_t a_row15 = lane & 15;
    const uint32_t a_hi    = lane >> 4;
    const uint32_t x7      = lane & 7;
    const uint32_t w_hi    = lane >> 3;

    uint32_t aRowOff[4], wRowOff[4];
#pragma unroll
    for (int mi = 0; mi < 4; mi++)
        aRowOff[mi] = (uint32_t)((wm*64 + mi*16 + a_row15) * 128);
#pragma unroll
    for (int ni = 0; ni < 4; ni++)
        wRowOff[ni] = (uint32_t)((BM*128) + (wn*32 + ni*8 + x7) * 128);

    for (int kt = 0; kt < KT; kt++) {
        asm volatile("cp.async.wait_group %0;" :: "n"(STAGES-2) : "memory");
        __syncthreads();
        int ktn = kt + STAGES - 1;
        if (ktn < KT) LOAD_STAGE_T(ktn % STAGES, ktn);
        asm volatile("cp.async.commit_group;" ::: "memory");

        const uint32_t sbase = smaddr + (kt % STAGES)*STAGE_BYTES;
#pragma unroll
        for (int kp = 0; kp < 2; kp++) {
            uint32_t wq[4][4];
            const uint32_t wsw = ((4*kp + w_hi) ^ x7) << 4;
#pragma unroll
            for (int ni = 0; ni < 4; ni++) {
                asm volatile("ldmatrix.sync.aligned.m8n8.x4.shared.b16 {%0,%1,%2,%3}, [%4];"
                    : "=r"(wq[ni][0]), "=r"(wq[ni][1]), "=r"(wq[ni][2]), "=r"(wq[ni][3])
                    : "r"(sbase + wRowOff[ni] + wsw));
            }
#pragma unroll
            for (int kk2 = 0; kk2 < 2; kk2++) {
                const int kk = 2*kp + kk2;
                const uint32_t asw = ((2*kk + a_hi) ^ x7) << 4;
                uint32_t af[4][4];
#pragma unroll
                for (int mi = 0; mi < 4; mi++) {
                    asm volatile("ldmatrix.sync.aligned.m8n8.x4.shared.b16 {%0,%1,%2,%3}, [%4];"
                        : "=r"(af[mi][0]), "=r"(af[mi][1]), "=r"(af[mi][2]), "=r"(af[mi][3])
                        : "r"(sbase + aRowOff[mi] + asw));
                }
#pragma unroll
                for (int mi = 0; mi < 4; mi++)
#pragma unroll
                    for (int ni = 0; ni < 4; ni++)
                        asm volatile(
                            "mma.sync.aligned.m16n8k16.row.col.f32.f16.f16.f32 "
                            "{%0,%1,%2,%3}, {%4,%5,%6,%7}, {%8,%9}, {%0,%1,%2,%3};"
                            : "+f"(acc[mi][ni][0]), "+f"(acc[mi][ni][1]),
                              "+f"(acc[mi][ni][2]), "+f"(acc[mi][ni][3])
                            : "r"(af[mi][0]), "r"(af[mi][1]), "r"(af[mi][2]), "r"(af[mi][3]),
                              "r"(wq[ni][2*kk2]), "r"(wq[ni][2*kk2+1]));
            }
        }
    }

    if (Ch) {
#pragma unroll
        for (int mi = 0; mi < 4; mi++) {
            int r0 = row0 + wm*64 + mi*16 + g;
#pragma unroll
            for (int ni = 0; ni < 4; ni++) {
                int c = col0 + wn*32 + ni*8 + 2*q;
                *(__half2*)(Ch + (size_t)r0     * Nout + c) = __floats2half2_rn(acc[mi][ni][0], acc[mi][ni][1]);
                *(__half2*)(Ch + (size_t)(r0+8) * Nout + c) = __floats2half2_rn(acc[mi][ni][2], acc[mi][ni][3]);
            }
        }
    } else {
#pragma unroll
        for (int mi = 0; mi < 4; mi++) {
            int r0 = row0 + wm*64 + mi*16 + g;
#pragma unroll
            for (int ni = 0; ni < 4; ni++) {
                int c = col0 + wn*32 + ni*8 + 2*q;
                float b0 = bias ? bias[c] : 0.f, b1 = bias ? bias[c+1] : 0.f;
                *(float2*)(Cf + (size_t)r0     * Nout + c) = make_float2(acc[mi][ni][0]+b0, acc[mi][ni][1]+b1);
                *(float2*)(Cf + (size_t)(r0+8) * Nout + c) = make_float2(acc[mi][ni][2]+b0, acc[mi][ni][3]+b1);
            }
        }
    }
#undef LOAD_STAGE_T
}

// single GEMM (A0 fp16-out w/ gather; output GEMM fp32-out w/ gather)
__global__ __launch_bounds__(256, 2)
void gemm_s(const __half* __restrict__ A, const __half* __restrict__ W,
            __half* __restrict__ Ch, float* __restrict__ Cf,
            int N, int K, const int* __restrict__ a_off, const float* __restrict__ bias)
{
    extern __shared__ uint32_t sm[];
    const uint32_t smaddr = (uint32_t)__cvta_generic_to_shared(sm);
    gemm_tile(A, W, Ch, Cf, blockIdx.y * BM, blockIdx.x * BN, N, K, a_off, bias,
              smaddr, threadIdx.x);
}

// wavefront GEMM: 3 operand sets via z, gated by d_T and active-row prefix d_M
__global__ __launch_bounds__(256, 2)
void gemm_w(const __half* __restrict__ h0h, const __half* __restrict__ h1h,
            int t0, int t1)
{
    int tt = (blockIdx.z == 0) ? t0 : t1;
    if (tt < 0 || tt >= d_T[0]) return;
    if (blockIdx.y * BM >= d_M[tt]) return;   // inactive rows

    const __half* A = (blockIdx.z == 1) ? h1h : h0h;
    const __half* W = (blockIdx.z == 0) ? d_Whh0h : ((blockIdx.z == 1) ? d_Whh1h : d_Wih1h);
    __half*       C = (blockIdx.z == 0) ? d_G0h : ((blockIdx.z == 1) ? d_G1h : d_A1h);

    extern __shared__ uint32_t sm[];
    const uint32_t smaddr = (uint32_t)__cvta_generic_to_shared(sm);
    gemm_tile(A, W, C, nullptr, blockIdx.y * BM, blockIdx.x * BN, H3, HSZ,
              nullptr, nullptr, smaddr, threadIdx.x);
}

// ---------------- merged GRU pointwise (fp16 gates, active-row gated) ----------------
__device__ __forceinline__ float sigm(float x) { return 1.f / (1.f + __expf(-x)); }
__device__ __forceinline__ float tanh_fast(float x) { return 2.f / (1.f + __expf(-2.f*x)) - 1.f; }

__device__ __forceinline__ void ld4h(const __half* p, float* o) {
    __half2 v0 = *(const __half2*)(p);
    __half2 v1 = *(const __half2*)(p + 2);
    float2 f0 = __half22float2(v0);
    float2 f1 = __half22float2(v1);
    o[0] = f0.x; o[1] = f0.y; o[2] = f1.x; o[3] = f1.y;
}

__global__ void k_pw(const float* __restrict__ bih0, const float* __restrict__ bhh0,
                     const float* __restrict__ bih1, const float* __restrict__ bhh1,
                     const float* __restrict__ h0in, float* __restrict__ h0out,
                     __half* __restrict__ h0hout,
                     const float* __restrict__ h1in, float* __restrict__ h1out,
                     __half* __restrict__ h1hout, __half* __restrict__ yout, int k)
{
    const int T = d_T[0];
    int i4 = blockIdx.x * blockDim.x + threadIdx.x;
    if (i4 >= BH/4) return;
    int i = i4 << 2;
    int b = i >> 9, j = i & (HSZ-1);
    int base = b*H3 + j;

    const __half* Xs; const __half* Gs;
    const float* bi;  const float* bh;
    const float* hin; float* hout; __half* hhout;
    bool writeY;

    if (blockIdx.y == 0) {
        if (k >= T || b >= d_M[k]) return;
        Xs = d_A0h; Gs = d_G0h; bi = bih0; bh = bhh0;
        hin = h0in; hout = h0out; hhout = h0hout; writeY = false;
    } else {
        if (k < 1 || k-1 >= T || b >= d_M[k-1]) return;
        Xs = d_A1h; Gs = d_G1h; bi = bih1; bh = bhh1;
        hin = h1in; hout = h1out; hhout = h1hout; writeY = true;
    }

    float xr[4], xz[4], xn[4], gr[4], gz[4], gn[4];
    ld4h(Xs + base,         xr);
    ld4h(Xs + base + HSZ,   xz);
    ld4h(Xs + base + 2*HSZ, xn);
    ld4h(Gs + base,         gr);
    ld4h(Gs + base + HSZ,   gz);
    ld4h(Gs + base + 2*HSZ, gn);

    float4 h  = *(const float4*)(hin + i);
    float4 bir = *(const float4*)(bi + j);
    float4 biz = *(const float4*)(bi + j + HSZ);
    float4 bin = *(const float4*)(bi + j + 2*HSZ);
    float4 bhr = *(const float4*)(bh + j);
    float4 bhz = *(const float4*)(bh + j + HSZ);
    float4 bhn = *(const float4*)(bh + j + 2*HSZ);

    const float* ph =(const float*)&h;
    const float* pir=(const float*)&bir; const float* piz=(const float*)&biz; const float* pin=(const float*)&bin;
    const float* phr=(const float*)&bhr; const float* phz=(const float*)&bhz; const float* phn=(const float*)&bhn;

    float hn[4];
#pragma unroll
    for (int e = 0; e < 4; e++) {
        float r = sigm(xr[e]+pir[e] + gr[e]+phr[e]);
        float z = sigm(xz[e]+piz[e] + gz[e]+phz[e]);
        float n = tanh_fast(xn[e]+pin[e] + r * (gn[e]+phn[e]));
        hn[e] = (1.f - z) * n + z * ph[e];
    }

    *(float4*)(hout + i) = make_float4(hn[0], hn[1], hn[2], hn[3]);
    __half2 p0 = __floats2half2_rn(hn[0], hn[1]);
    __half2 p1 = __floats2half2_rn(hn[2], hn[3]);
    ((__half2*)(hhout + i))[0] = p0;
    ((__half2*)(hhout + i))[1] = p1;
    if (writeY) {
        ((__half2*)(yout + i))[0] = p0;
        ((__half2*)(yout + i))[1] = p1;
    }
}

// ---------------- host launch ----------------
extern "C" void kernel_launch(void* const* d_in, const int* in_sizes, int n_in,
                              void* d_out, int out_size)
{
    const float* x    = (const float*)d_in[0];
    const float* Wih0 = (const float*)d_in[1];
    const float* Whh0 = (const float*)d_in[2];
    const float* bih0 = (const float*)d_in[3];
    const float* bhh0 = (const float*)d_in[4];
    const float* Wih1 = (const float*)d_in[5];
    const float* Whh1 = (const float*)d_in[6];
    const float* bih1 = (const float*)d_in[7];
    const float* bhh1 = (const float*)d_in[8];
    const float* Wout = (const float*)d_in[9];
    const float* bout = (const float*)d_in[10];
    const int*   psi  = (const int*)d_in[11];
    float* out = (float*)d_out;

    cudaFuncSetAttribute(gemm_s, cudaFuncAttributeMaxDynamicSharedMemorySize, SMEM_G);
    cudaFuncSetAttribute(gemm_w, cudaFuncAttributeMaxDynamicSharedMemorySize, SMEM_G);

    float *p_h0fA,*p_h0fB,*p_h1fA,*p_h1fB;
    __half *p_h0hA,*p_h0hB,*p_h1hA,*p_h1hB,*p_A0h,*p_Y1h,*p_xh,*p_Wih0h,*p_Wouth;
    int *p_rowoff,*p_xoff;
    cudaGetSymbolAddress((void**)&p_h0fA, d_h0fA);
    cudaGetSymbolAddress((void**)&p_h0fB, d_h0fB);
    cudaGetSymbolAddress((void**)&p_h1fA, d_h1fA);
    cudaGetSymbolAddress((void**)&p_h1fB, d_h1fB);
    cudaGetSymbolAddress((void**)&p_h0hA, d_h0hA);
    cudaGetSymbolAddress((void**)&p_h0hB, d_h0hB);
    cudaGetSymbolAddress((void**)&p_h1hA, d_h1hA);
    cudaGetSymbolAddress((void**)&p_h1hB, d_h1hB);
    cudaGetSymbolAddress((void**)&p_A0h,  d_A0h);
    cudaGetSymbolAddress((void**)&p_Y1h,  d_Y1h);
    cudaGetSymbolAddress((void**)&p_xh,   d_xh);
    cudaGetSymbolAddress((void**)&p_Wih0h,d_Wih0h);
    cudaGetSymbolAddress((void**)&p_Wouth,d_Wouth);
    cudaGetSymbolAddress((void**)&p_rowoff, d_rowoff);
    cudaGetSymbolAddress((void**)&p_xoff,   d_xoff);

    const int PWI = (BH + 255) / 256;
    const int PW4 = (BH/4 + 255) / 256;

    k_init_first<<<PWI, 256>>>(psi);
    k_count<<<(NSZ + 255) / 256, 256>>>(psi);
    k_pos<<<BSZ/256, 256>>>();
    k_M<<<1, 256>>>();
    k_rank<<<(NSZ + 255) / 256, 256>>>(psi);
    k_convAll<<<(BSZ*INSZ/4 + 255)/256, 256>>>(x, Wih0, Whh0, Wih1, Whh1, Wout);

    // A0 (permuted rows via gather) = x[perm] . Wih0^T  (fp16 out; biases in pw)
    gemm_s<<<dim3(H3/BN, BSZ/BM), 256, SMEM_G>>>(
        p_xh, p_Wih0h, p_A0h, nullptr, H3, INSZ, p_xoff, nullptr);

    float  *h0f_in = p_h0fA, *h0f_out = p_h0fB;
    float  *h1f_in = p_h1fA, *h1f_out = p_h1fB;
    __half *h0h_in = p_h0hA, *h0h_out = p_h0hB;
    __half *h1h_in = p_h1hA, *h1h_out = p_h1hB;

    // wavefront: iteration k = layer0 step k + layer1 step k-1, active-prefix gated
    for (int k = 0; k <= T_MAX; k++) {
        gemm_w<<<dim3(H3/BN, BSZ/BM, 3), 256, SMEM_G>>>(h0h_in, h1h_in, k, k-1);

        __half* yptr = p_Y1h + (size_t)(k > 0 ? k-1 : 0) * BH;
        k_pw<<<dim3(PW4, 2), 256>>>(bih0, bhh0, bih1, bhh1,
                                    h0f_in, h0f_out, h0h_out,
                                    h1f_in, h1f_out, h1h_out, yptr, k);

        float* tf; __half* th;
        tf = h0f_in; h0f_in = h0f_out; h0f_out = tf;
        tf = h1f_in; h1f_in = h1f_out; h1f_out = tf;
        th = h0h_in; h0h_in = h0h_out; h0h_out = th;
        th = h1h_in; h1h_in = h1h_out; h1h_out = th;
    }

    // gathered output GEMM: out[N, OUT] = Y1h[rowoff[j]] . Wout^T + bout
    gemm_s<<<dim3(OUTSZ/BN, NSZ/BM), 256, SMEM_G>>>(
        p_Y1h, p_Wouth, nullptr, out, OUTSZ, HSZ, p_rowoff, bout);

    (void)in_sizes; (void)n_in; (void)out_size;
}

// round 13
// speedup vs baseline: 1.5632x; 1.0725x over previous
#include <cuda_runtime.h>
#include <cuda_fp16.h>
#include <math.h>
#include <stdint.h>

#define BSZ   2048
#define INSZ  512
#define HSZ   512
#define OUTSZ 256
#define NSZ   32768
#define H3    (3*HSZ)
#define T_MAX 40
#define BH    (BSZ*HSZ)

#define BM 128
#define BN 128
#define STAGE_BYTES (2*BM*128)
#define STAGES 3
#define SMEM_G (STAGES*STAGE_BYTES)      // 98304

// ---------------- device scratch ----------------
__device__ float  d_h0fA[BH], d_h0fB[BH], d_h1fA[BH], d_h1fB[BH];
__device__ __half d_h0hA[BH], d_h0hB[BH], d_h1hA[BH], d_h1hB[BH];
__device__ __half d_A0h[BSZ*H3];
__device__ __half d_G0h[BSZ*H3];
__device__ __half d_G1h[BSZ*H3];
__device__ __half d_A1h[BSZ*H3];
__device__ __half d_Y1h[(size_t)T_MAX*BH];
__device__ __half d_xh   [BSZ*INSZ];
__device__ __half d_Wih0h[H3*INSZ];
__device__ __half d_Whh0h[H3*HSZ];
__device__ __half d_Wih1h[H3*HSZ];
__device__ __half d_Whh1h[H3*HSZ];
__device__ __half d_Wouth[OUTSZ*HSZ];
__device__ int    d_first[BSZ];
__device__ int    d_cnt[BSZ];
__device__ int    d_pos[BSZ];            // orig row -> permuted position
__device__ int    d_xoff[BSZ];           // permuted pos -> orig x row offset
__device__ int    d_rowoff[NSZ];
__device__ int    d_hist[64];
__device__ int    d_off[64];
__device__ int    d_start[64];
__device__ int    d_M[T_MAX+1];          // active rows at step t
__device__ int    d_T[1];

// ---------------- setup (counting sort) ----------------
__global__ void k_init_first(const int* __restrict__ psi) {
    int i = blockIdx.x * blockDim.x + threadIdx.x;
    if (i == 0) d_T[0] = 0;
    if (i < 64) { d_hist[i] = 0; d_off[i] = 0; }
    if (i < BSZ) d_cnt[i] = 0;
    if (i < BH) {
        d_h0fA[i]=0.f; d_h0fB[i]=0.f; d_h1fA[i]=0.f; d_h1fB[i]=0.f;
        __half z = __float2half(0.f);
        d_h0hA[i]=z; d_h0hB[i]=z; d_h1hA[i]=z; d_h1hB[i]=z;
    }
    if (i < NSZ) {
        if (i == 0 || psi[i] != psi[i-1]) d_first[psi[i]] = i;
    }
}

__global__ void k_count(const int* __restrict__ psi) {
    int j = blockIdx.x * blockDim.x + threadIdx.x;
    if (j < NSZ) atomicAdd(&d_cnt[psi[j]], 1);
}

__global__ void k_hist() {
    int i = blockIdx.x * blockDim.x + threadIdx.x;
    if (i >= BSZ) return;
    int c = d_cnt[i] < 63 ? d_cnt[i] : 63;
    atomicAdd(&d_hist[c], 1);
    atomicMax(&d_T[0], d_cnt[i]);
}

// start[c] = #rows with cnt > c (suffix sum); M[t] = start[t]
__global__ void k_start() {
    if (threadIdx.x == 0) {
        int run = 0;
        for (int c = 63; c >= 0; c--) {
            d_start[c] = run;
            run += d_hist[c];
        }
        for (int t = 0; t <= T_MAX; t++)
            d_M[t] = (t < 64) ? d_start[t] : 0;
    }
}

__global__ void k_scatter() {
    int i = blockIdx.x * blockDim.x + threadIdx.x;
    if (i >= BSZ) return;
    int c = d_cnt[i] < 63 ? d_cnt[i] : 63;
    int pos = d_start[c] + atomicAdd(&d_off[c], 1);
    d_pos[i] = pos;
    d_xoff[pos] = i * INSZ;
}

__global__ void k_rank(const int* __restrict__ psi) {
    int j = blockIdx.x * blockDim.x + threadIdx.x;
    if (j >= NSZ) return;
    int v = psi[j];
    int r = j - d_first[v];
    d_rowoff[j] = r * BH + d_pos[v] * HSZ;
}

__device__ __forceinline__ void conv4(const float* src, __half* dst, int i) {
    float4 v = *(const float4*)(src + i);
    ((__half2*)(dst + i))[0] = __floats2half2_rn(v.x, v.y);
    ((__half2*)(dst + i))[1] = __floats2half2_rn(v.z, v.w);
}

__global__ void k_convAll(const float* __restrict__ x,  const float* __restrict__ wih0,
                          const float* __restrict__ whh0, const float* __restrict__ wih1,
                          const float* __restrict__ whh1, const float* __restrict__ wout) {
    int i = (blockIdx.x * blockDim.x + threadIdx.x) << 2;
    if (i < BSZ*INSZ)  conv4(x,    d_xh,    i);
    if (i < H3*INSZ)   conv4(wih0, d_Wih0h, i);
    if (i < H3*HSZ) {
        conv4(whh0, d_Whh0h, i);
        conv4(wih1, d_Wih1h, i);
        conv4(whh1, d_Whh1h, i);
    }
    if (i < OUTSZ*HSZ) conv4(wout, d_Wouth, i);
}

// ---------------- GEMM tile (proven: 128x128, 256 thr, 3-stage cp.async + ldmatrix) ----------------
__device__ __forceinline__ void gemm_tile(
    const __half* __restrict__ A, const __half* __restrict__ W,
    __half* __restrict__ Ch, float* __restrict__ Cf,
    int row0, int col0, int Nout, int K,
    const int* __restrict__ a_off, const float* __restrict__ bias,
    uint32_t smaddr, int tid)
{
    const int lane = tid & 31;
    const int warp = tid >> 5;
    const int wm   = warp >> 2;
    const int wn   = warp & 3;
    const int g    = lane >> 2;
    const int q    = lane & 3;

    const int lm   = tid >> 1;
    const int lkg0 = (tid & 1) * 4;

    long arow = a_off ? (long)a_off[row0 + lm] : (long)(row0 + lm) * K;
    const __half* agp = A + arow;
    const __half* wgp = W + (long)(col0 + lm) * K;

    uint32_t soffB[4];
#pragma unroll
    for (int j = 0; j < 4; j++)
        soffB[j] = (uint32_t)(lm * 128 + (((lkg0 + j) ^ (lm & 7)) << 4));

#define LOAD_STAGE_T(st, kt) do {                                            \
        uint32_t dA = smaddr + (st)*STAGE_BYTES;                             \
        uint32_t dW = dA + BM*128;                                           \
        const __half* ga = agp + (size_t)(kt)*64;                            \
        const __half* gw = wgp + (size_t)(kt)*64;                            \
        _Pragma("unroll")                                                    \
        for (int j = 0; j < 4; j++) {                                        \
            asm volatile("cp.async.cg.shared.global [%0], [%1], 16;"         \
                         :: "r"(dA + soffB[j]), "l"(ga + (lkg0 + j)*8));     \
            asm volatile("cp.async.cg.shared.global [%0], [%1], 16;"         \
                         :: "r"(dW + soffB[j]), "l"(gw + (lkg0 + j)*8));     \
        }                                                                    \
    } while (0)

    float acc[4][4][4];
#pragma unroll
    for (int a = 0; a < 4; a++)
#pragma unroll
        for (int b = 0; b < 4; b++)
#pragma unroll
            for (int c = 0; c < 4; c++) acc[a][b][c] = 0.f;

    const int KT = K / 64;

#pragma unroll
    for (int s = 0; s < STAGES-1; s++) {
        LOAD_STAGE_T(s, s);
        asm volatile("cp.async.commit_group;" ::: "memory");
    }

    const uint32_t a_row15 = lane & 15;
    const uint32_t a_hi    = lane >> 4;
    const uint32_t x7      = lane & 7;
    const uint32_t w_hi    = lane >> 3;

    uint32_t aRowOff[4], wRowOff[4];
#pragma unroll
    for (int mi = 0; mi < 4; mi++)
        aRowOff[mi] = (uint32_t)((wm*64 + mi*16 + a_row15) * 128);
#pragma unroll
    for (int ni = 0; ni < 4; ni++)
        wRowOff[ni] = (uint32_t)((BM*128) + (wn*32 + ni*8 + x7) * 128);

    for (int kt = 0; kt < KT; kt++) {
        asm volatile("cp.async.wait_group %0;" :: "n"(STAGES-2) : "memory");
        __syncthreads();
        int ktn = kt + STAGES - 1;
        if (ktn < KT) LOAD_STAGE_T(ktn % STAGES, ktn);
        asm volatile("cp.async.commit_group;" ::: "memory");

        const uint32_t sbase = smaddr + (kt % STAGES)*STAGE_BYTES;
#pragma unroll
        for (int kp = 0; kp < 2; kp++) {
            uint32_t wq[4][4];
            const uint32_t wsw = ((4*kp + w_hi) ^ x7) << 4;
#pragma unroll
            for (int ni = 0; ni < 4; ni++) {
                asm volatile("ldmatrix.sync.aligned.m8n8.x4.shared.b16 {%0,%1,%2,%3}, [%4];"
                    : "=r"(wq[ni][0]), "=r"(wq[ni][1]), "=r"(wq[ni][2]), "=r"(wq[ni][3])
                    : "r"(sbase + wRowOff[ni] + wsw));
            }
#pragma unroll
            for (int kk2 = 0; kk2 < 2; kk2++) {
                const int kk = 2*kp + kk2;
                const uint32_t asw = ((2*kk + a_hi) ^ x7) << 4;
                uint32_t af[4][4];
#pragma unroll
                for (int mi = 0; mi < 4; mi++) {
                    asm volatile("ldmatrix.sync.aligned.m8n8.x4.shared.b16 {%0,%1,%2,%3}, [%4];"
                        : "=r"(af[mi][0]), "=r"(af[mi][1]), "=r"(af[mi][2]), "=r"(af[mi][3])
                        : "r"(sbase + aRowOff[mi] + asw));
                }
#pragma unroll
                for (int mi = 0; mi < 4; mi++)
#pragma unroll
                    for (int ni = 0; ni < 4; ni++)
                        asm volatile(
                            "mma.sync.aligned.m16n8k16.row.col.f32.f16.f16.f32 "
                            "{%0,%1,%2,%3}, {%4,%5,%6,%7}, {%8,%9}, {%0,%1,%2,%3};"
                            : "+f"(acc[mi][ni][0]), "+f"(acc[mi][ni][1]),
                              "+f"(acc[mi][ni][2]), "+f"(acc[mi][ni][3])
                            : "r"(af[mi][0]), "r"(af[mi][1]), "r"(af[mi][2]), "r"(af[mi][3]),
                              "r"(wq[ni][2*kk2]), "r"(wq[ni][2*kk2+1]));
            }
        }
    }

    if (Ch) {
#pragma unroll
        for (int mi = 0; mi < 4; mi++) {
            int r0 = row0 + wm*64 + mi*16 + g;
#pragma unroll
            for (int ni = 0; ni < 4; ni++) {
                int c = col0 + wn*32 + ni*8 + 2*q;
                *(__half2*)(Ch + (size_t)r0     * Nout + c) = __floats2half2_rn(acc[mi][ni][0], acc[mi][ni][1]);
                *(__half2*)(Ch + (size_t)(r0+8) * Nout + c) = __floats2half2_rn(acc[mi][ni][2], acc[mi][ni][3]);
            }
        }
    } else {
#pragma unroll
        for (int mi = 0; mi < 4; mi++) {
            int r0 = row0 + wm*64 + mi*16 + g;
#pragma unroll
            for (int ni = 0; ni < 4; ni++) {
                int c = col0 + wn*32 + ni*8 + 2*q;
                float b0 = bias ? bias[c] : 0.f, b1 = bias ? bias[c+1] : 0.f;
                *(float2*)(Cf + (size_t)r0     * Nout + c) = make_float2(acc[mi][ni][0]+b0, acc[mi][ni][1]+b1);
                *(float2*)(Cf + (size_t)(r0+8) * Nout + c) = make_float2(acc[mi][ni][2]+b0, acc[mi][ni][3]+b1);
            }
        }
    }
#undef LOAD_STAGE_T
}

__global__ __launch_bounds__(256, 2)
void gemm_s(const __half* __restrict__ A, const __half* __restrict__ W,
            __half* __restrict__ Ch, float* __restrict__ Cf,
            int N, int K, const int* __restrict__ a_off, const float* __restrict__ bias)
{
    extern __shared__ uint32_t sm[];
    const uint32_t smaddr = (uint32_t)__cvta_generic_to_shared(sm);
    gemm_tile(A, W, Ch, Cf, blockIdx.y * BM, blockIdx.x * BN, N, K, a_off, bias,
              smaddr, threadIdx.x);
}

__global__ __launch_bounds__(256, 2)
void gemm_w(const __half* __restrict__ h0h, const __half* __restrict__ h1h,
            int t0, int t1)
{
    int tt = (blockIdx.z == 0) ? t0 : t1;
    if (tt < 0 || tt >= d_T[0]) return;
    if (blockIdx.y * BM >= d_M[tt]) return;

    const __half* A = (blockIdx.z == 1) ? h1h : h0h;
    const __half* W = (blockIdx.z == 0) ? d_Whh0h : ((blockIdx.z == 1) ? d_Whh1h : d_Wih1h);
    __half*       C = (blockIdx.z == 0) ? d_G0h : ((blockIdx.z == 1) ? d_G1h : d_A1h);

    extern __shared__ uint32_t sm[];
    const uint32_t smaddr = (uint32_t)__cvta_generic_to_shared(sm);
    gemm_tile(A, W, C, nullptr, blockIdx.y * BM, blockIdx.x * BN, H3, HSZ,
              nullptr, nullptr, smaddr, threadIdx.x);
}

// ---------------- merged GRU pointwise ----------------
__device__ __forceinline__ float sigm(float x) { return 1.f / (1.f + __expf(-x)); }
__device__ __forceinline__ float tanh_fast(float x) { return 2.f / (1.f + __expf(-2.f*x)) - 1.f; }

__device__ __forceinline__ void ld4h(const __half* p, float* o) {
    __half2 v0 = *(const __half2*)(p);
    __half2 v1 = *(const __half2*)(p + 2);
    float2 f0 = __half22float2(v0);
    float2 f1 = __half22float2(v1);
    o[0] = f0.x; o[1] = f0.y; o[2] = f1.x; o[3] = f1.y;
}

__global__ void k_pw(const float* __restrict__ bih0, const float* __restrict__ bhh0,
                     const float* __restrict__ bih1, const float* __restrict__ bhh1,
                     const float* __restrict__ h0in, float* __restrict__ h0out,
                     __half* __restrict__ h0hout,
                     const float* __restrict__ h1in, float* __restrict__ h1out,
                     __half* __restrict__ h1hout, __half* __restrict__ yout, int k)
{
    const int T = d_T[0];
    int i4 = blockIdx.x * blockDim.x + threadIdx.x;
    if (i4 >= BH/4) return;
    int i = i4 << 2;
    int b = i >> 9, j = i & (HSZ-1);
    int base = b*H3 + j;

    const __half* Xs; const __half* Gs;
    const float* bi;  const float* bh;
    const float* hin; float* hout; __half* hhout;
    bool writeY;

    if (blockIdx.y == 0) {
        if (k >= T || b >= d_M[k]) return;
        Xs = d_A0h; Gs = d_G0h; bi = bih0; bh = bhh0;
        hin = h0in; hout = h0out; hhout = h0hout; writeY = false;
    } else {
        if (k < 1 || k-1 >= T || b >= d_M[k-1]) return;
        Xs = d_A1h; Gs = d_G1h; bi = bih1; bh = bhh1;
        hin = h1in; hout = h1out; hhout = h1hout; writeY = true;
    }

    float xr[4], xz[4], xn[4], gr[4], gz[4], gn[4];
    ld4h(Xs + base,         xr);
    ld4h(Xs + base + HSZ,   xz);
    ld4h(Xs + base + 2*HSZ, xn);
    ld4h(Gs + base,         gr);
    ld4h(Gs + base + HSZ,   gz);
    ld4h(Gs + base + 2*HSZ, gn);

    float4 h  = *(const float4*)(hin + i);
    float4 bir = *(const float4*)(bi + j);
    float4 biz = *(const float4*)(bi + j + HSZ);
    float4 bin = *(const float4*)(bi + j + 2*HSZ);
    float4 bhr = *(const float4*)(bh + j);
    float4 bhz = *(const float4*)(bh + j + HSZ);
    float4 bhn = *(const float4*)(bh + j + 2*HSZ);

    const float* ph =(const float*)&h;
    const float* pir=(const float*)&bir; const float* piz=(const float*)&biz; const float* pin=(const float*)&bin;
    const float* phr=(const float*)&bhr; const float* phz=(const float*)&bhz; const float* phn=(const float*)&bhn;

    float hn[4];
#pragma unroll
    for (int e = 0; e < 4; e++) {
        float r = sigm(xr[e]+pir[e] + gr[e]+phr[e]);
        float z = sigm(xz[e]+piz[e] + gz[e]+phz[e]);
        float n = tanh_fast(xn[e]+pin[e] + r * (gn[e]+phn[e]));
        hn[e] = (1.f - z) * n + z * ph[e];
    }

    *(float4*)(hout + i) = make_float4(hn[0], hn[1], hn[2], hn[3]);
    __half2 p0 = __floats2half2_rn(hn[0], hn[1]);
    __half2 p1 = __floats2half2_rn(hn[2], hn[3]);
    ((__half2*)(hhout + i))[0] = p0;
    ((__half2*)(hhout + i))[1] = p1;
    if (writeY) {
        ((__half2*)(yout + i))[0] = p0;
        ((__half2*)(yout + i))[1] = p1;
    }
}

// ---------------- host launch ----------------
extern "C" void kernel_launch(void* const* d_in, const int* in_sizes, int n_in,
                              void* d_out, int out_size)
{
    const float* x    = (const float*)d_in[0];
    const float* Wih0 = (const float*)d_in[1];
    const float* Whh0 = (const float*)d_in[2];
    const float* bih0 = (const float*)d_in[3];
    const float* bhh0 = (const float*)d_in[4];
    const float* Wih1 = (const float*)d_in[5];
    const float* Whh1 = (const float*)d_in[6];
    const float* bih1 = (const float*)d_in[7];
    const float* bhh1 = (const float*)d_in[8];
    const float* Wout = (const float*)d_in[9];
    const float* bout = (const float*)d_in[10];
    const int*   psi  = (const int*)d_in[11];
    float* out = (float*)d_out;

    cudaFuncSetAttribute(gemm_s, cudaFuncAttributeMaxDynamicSharedMemorySize, SMEM_G);
    cudaFuncSetAttribute(gemm_w, cudaFuncAttributeMaxDynamicSharedMemorySize, SMEM_G);

    float *p_h0fA,*p_h0fB,*p_h1fA,*p_h1fB;
    __half *p_h0hA,*p_h0hB,*p_h1hA,*p_h1hB,*p_A0h,*p_Y1h,*p_xh,*p_Wih0h,*p_Wouth;
    int *p_rowoff,*p_xoff;
    cudaGetSymbolAddress((void**)&p_h0fA, d_h0fA);
    cudaGetSymbolAddress((void**)&p_h0fB, d_h0fB);
    cudaGetSymbolAddress((void**)&p_h1fA, d_h1fA);
    cudaGetSymbolAddress((void**)&p_h1fB, d_h1fB);
    cudaGetSymbolAddress((void**)&p_h0hA, d_h0hA);
    cudaGetSymbolAddress((void**)&p_h0hB, d_h0hB);
    cudaGetSymbolAddress((void**)&p_h1hA, d_h1hA);
    cudaGetSymbolAddress((void**)&p_h1hB, d_h1hB);
    cudaGetSymbolAddress((void**)&p_A0h,  d_A0h);
    cudaGetSymbolAddress((void**)&p_Y1h,  d_Y1h);
    cudaGetSymbolAddress((void**)&p_xh,   d_xh);
    cudaGetSymbolAddress((void**)&p_Wih0h,d_Wih0h);
    cudaGetSymbolAddress((void**)&p_Wouth,d_Wouth);
    cudaGetSymbolAddress((void**)&p_rowoff, d_rowoff);
    cudaGetSymbolAddress((void**)&p_xoff,   d_xoff);

    const int PWI = (BH + 255) / 256;
    const int PW4 = (BH/4 + 255) / 256;

    k_init_first<<<PWI, 256>>>(psi);
    k_count<<<(NSZ + 255) / 256, 256>>>(psi);
    k_hist<<<BSZ/256, 256>>>();
    k_start<<<1, 32>>>();
    k_scatter<<<BSZ/256, 256>>>();
    k_rank<<<(NSZ + 255) / 256, 256>>>(psi);
    k_convAll<<<(BSZ*INSZ/4 + 255)/256, 256>>>(x, Wih0, Whh0, Wih1, Whh1, Wout);

    // A0 (permuted rows via gather) = x[perm] . Wih0^T  (fp16 out; biases in pw)
    gemm_s<<<dim3(H3/BN, BSZ/BM), 256, SMEM_G>>>(
        p_xh, p_Wih0h, p_A0h, nullptr, H3, INSZ, p_xoff, nullptr);

    float  *h0f_in = p_h0fA, *h0f_out = p_h0fB;
    float  *h1f_in = p_h1fA, *h1f_out = p_h1fB;
    __half *h0h_in = p_h0hA, *h0h_out = p_h0hB;
    __half *h1h_in = p_h1hA, *h1h_out = p_h1hB;

    // wavefront: iteration k = layer0 step k + layer1 step k-1, active-prefix gated
    for (int k = 0; k <= T_MAX; k++) {
        gemm_w<<<dim3(H3/BN, BSZ/BM, 3), 256, SMEM_G>>>(h0h_in, h1h_in, k, k-1);

        __half* yptr = p_Y1h + (size_t)(k > 0 ? k-1 : 0) * BH;
        k_pw<<<dim3(PW4, 2), 256>>>(bih0, bhh0, bih1, bhh1,
                                    h0f_in, h0f_out, h0h_out,
                                    h1f_in, h1f_out, h1h_out, yptr, k);

        float* tf; __half* th;
        tf = h0f_in; h0f_in = h0f_out; h0f_out = tf;
        tf = h1f_in; h1f_in = h1f_out; h1f_out = tf;
        th = h0h_in; h0h_in = h0h_out; h0h_out = th;
        th = h1h_in; h1h_in = h1h_out; h1h_out = th;
    }

    // gathered output GEMM: out[N, OUT] = Y1h[rowoff[j]] . Wout^T + bout
    gemm_s<<<dim3(OUTSZ/BN, NSZ/BM), 256, SMEM_G>>>(
        p_Y1h, p_Wouth, nullptr, out, OUTSZ, HSZ, p_rowoff, bout);

    (void)in_sizes; (void)n_in; (void)out_size;
}

// round 14
// speedup vs baseline: 1.5948x; 1.0202x over previous
#include <cuda_runtime.h>
#include <cuda_fp16.h>
#include <math.h>
#include <stdint.h>

#define BSZ   2048
#define INSZ  512
#define HSZ   512
#define OUTSZ 256
#define NSZ   32768
#define H3    (3*HSZ)
#define T_MAX 40
#define BH    (BSZ*HSZ)

#define BM 128
#define BN 128
#define STAGE_BYTES (2*BM*128)
#define STAGES 3
#define SMEM_G (STAGES*STAGE_BYTES)      // 98304
#define KCONST 512
#define KT8    (KCONST/64)               // 8

// ---------------- device scratch ----------------
__device__ float  d_h0fA[BH], d_h0fB[BH], d_h1fA[BH], d_h1fB[BH];
__device__ __half d_h0hA[BH], d_h0hB[BH], d_h1hA[BH], d_h1hB[BH];
__device__ __half d_A0h[BSZ*H3];
__device__ __half d_G0h[BSZ*H3];
__device__ __half d_G1h[BSZ*H3];
__device__ __half d_A1h[BSZ*H3];
__device__ __half d_Y1h[(size_t)T_MAX*BH];
__device__ __half d_xh   [BSZ*INSZ];
__device__ __half d_Wih0h[H3*INSZ];
__device__ __half d_Whh0h[H3*HSZ];
__device__ __half d_Wih1h[H3*HSZ];
__device__ __half d_Whh1h[H3*HSZ];
__device__ __half d_Wouth[OUTSZ*HSZ];
__device__ int    d_first[BSZ];
__device__ int    d_cnt[BSZ];
__device__ int    d_pos[BSZ];
__device__ int    d_xoff[BSZ];
__device__ int    d_rowoff[NSZ];
__device__ int    d_hist[64];
__device__ int    d_off[64];
__device__ int    d_start[64];
__device__ int    d_M[T_MAX+1];
__device__ int    d_T[1];

// ---------------- setup (counting sort) ----------------
__global__ void k_init_first(const int* __restrict__ psi) {
    int i = blockIdx.x * blockDim.x + threadIdx.x;
    if (i == 0) d_T[0] = 0;
    if (i < 64) { d_hist[i] = 0; d_off[i] = 0; }
    if (i < BSZ) d_cnt[i] = 0;
    if (i < BH) {
        d_h0fA[i]=0.f; d_h0fB[i]=0.f; d_h1fA[i]=0.f; d_h1fB[i]=0.f;
        __half z = __float2half(0.f);
        d_h0hA[i]=z; d_h0hB[i]=z; d_h1hA[i]=z; d_h1hB[i]=z;
    }
    if (i < NSZ) {
        if (i == 0 || psi[i] != psi[i-1]) d_first[psi[i]] = i;
    }
}

__global__ void k_count(const int* __restrict__ psi) {
    int j = blockIdx.x * blockDim.x + threadIdx.x;
    if (j < NSZ) atomicAdd(&d_cnt[psi[j]], 1);
}

__global__ void k_hist() {
    int i = blockIdx.x * blockDim.x + threadIdx.x;
    if (i >= BSZ) return;
    int c = d_cnt[i] < 63 ? d_cnt[i] : 63;
    atomicAdd(&d_hist[c], 1);
    atomicMax(&d_T[0], d_cnt[i]);
}

__global__ void k_start() {
    if (threadIdx.x == 0) {
        int run = 0;
        for (int c = 63; c >= 0; c--) {
            d_start[c] = run;
            run += d_hist[c];
        }
        for (int t = 0; t <= T_MAX; t++)
            d_M[t] = (t < 64) ? d_start[t] : 0;
    }
}

__global__ void k_scatter() {
    int i = blockIdx.x * blockDim.x + threadIdx.x;
    if (i >= BSZ) return;
    int c = d_cnt[i] < 63 ? d_cnt[i] : 63;
    int pos = d_start[c] + atomicAdd(&d_off[c], 1);
    d_pos[i] = pos;
    d_xoff[pos] = i * INSZ;
}

__global__ void k_rank(const int* __restrict__ psi) {
    int j = blockIdx.x * blockDim.x + threadIdx.x;
    if (j >= NSZ) return;
    int v = psi[j];
    int r = j - d_first[v];
    d_rowoff[j] = r * BH + d_pos[v] * HSZ;
}

__device__ __forceinline__ void conv4(const float* src, __half* dst, int i) {
    float4 v = *(const float4*)(src + i);
    ((__half2*)(dst + i))[0] = __floats2half2_rn(v.x, v.y);
    ((__half2*)(dst + i))[1] = __floats2half2_rn(v.z, v.w);
}

__global__ void k_convAll(const float* __restrict__ x,  const float* __restrict__ wih0,
                          const float* __restrict__ whh0, const float* __restrict__ wih1,
                          const float* __restrict__ whh1, const float* __restrict__ wout) {
    int i = (blockIdx.x * blockDim.x + threadIdx.x) << 2;
    if (i < BSZ*INSZ)  conv4(x,    d_xh,    i);
    if (i < H3*INSZ)   conv4(wih0, d_Wih0h, i);
    if (i < H3*HSZ) {
        conv4(whh0, d_Whh0h, i);
        conv4(wih1, d_Wih1h, i);
        conv4(whh1, d_Whh1h, i);
    }
    if (i < OUTSZ*HSZ) conv4(wout, d_Wouth, i);
}

// ---------------- GEMM tile: 128x128, 256 thr, 3-stage, K=512 compile-time ----------------
template<bool GATHER, bool HALF_OUT>
__device__ __forceinline__ void gemm_tile(
    const __half* __restrict__ A, const __half* __restrict__ W,
    __half* __restrict__ Ch, float* __restrict__ Cf,
    int row0, int col0, int Nout,
    const int* __restrict__ a_off, const float* __restrict__ bias,
    uint32_t smaddr, int tid)
{
    const int lane = tid & 31;
    const int warp = tid >> 5;
    const int wm   = warp >> 2;
    const int wn   = warp & 3;
    const int g    = lane >> 2;
    const int q    = lane & 3;

    const int lm   = tid >> 1;
    const int lkg0 = (tid & 1) * 4;

    const __half* agp;
    if (GATHER) agp = A + a_off[row0 + lm];
    else        agp = A + (size_t)(row0 + lm) * KCONST;
    const __half* wgp = W + (size_t)(col0 + lm) * KCONST;

    uint32_t soffB[4];
#pragma unroll
    for (int j = 0; j < 4; j++)
        soffB[j] = (uint32_t)(lm * 128 + (((lkg0 + j) ^ (lm & 7)) << 4));

#define LOAD_STAGE_T(st, kt) do {                                            \
        uint32_t dA = smaddr + (st)*STAGE_BYTES;                             \
        uint32_t dW = dA + BM*128;                                           \
        const __half* ga = agp + (kt)*64;                                    \
        const __half* gw = wgp + (kt)*64;                                    \
        _Pragma("unroll")                                                    \
        for (int j = 0; j < 4; j++) {                                        \
            asm volatile("cp.async.cg.shared.global [%0], [%1], 16;"         \
                         :: "r"(dA + soffB[j]), "l"(ga + (lkg0 + j)*8));     \
            asm volatile("cp.async.cg.shared.global [%0], [%1], 16;"         \
                         :: "r"(dW + soffB[j]), "l"(gw + (lkg0 + j)*8));     \
        }                                                                    \
    } while (0)

    float acc[4][4][4];
#pragma unroll
    for (int a = 0; a < 4; a++)
#pragma unroll
        for (int b = 0; b < 4; b++)
#pragma unroll
            for (int c = 0; c < 4; c++) acc[a][b][c] = 0.f;

#pragma unroll
    for (int s = 0; s < STAGES-1; s++) {
        LOAD_STAGE_T(s, s);
        asm volatile("cp.async.commit_group;" ::: "memory");
    }

    const uint32_t a_row15 = lane & 15;
    const uint32_t a_hi    = lane >> 4;
    const uint32_t x7      = lane & 7;
    const uint32_t w_hi    = lane >> 3;

    uint32_t aRowOff[4], wRowOff[4];
#pragma unroll
    for (int mi = 0; mi < 4; mi++)
        aRowOff[mi] = (uint32_t)((wm*64 + mi*16 + a_row15) * 128);
#pragma unroll
    for (int ni = 0; ni < 4; ni++)
        wRowOff[ni] = (uint32_t)((BM*128) + (wn*32 + ni*8 + x7) * 128);

#pragma unroll
    for (int kt = 0; kt < KT8; kt++) {
        asm volatile("cp.async.wait_group %0;" :: "n"(STAGES-2) : "memory");
        __syncthreads();
        if (kt + STAGES - 1 < KT8) LOAD_STAGE_T((kt + STAGES - 1) % STAGES, kt + STAGES - 1);
        asm volatile("cp.async.commit_group;" ::: "memory");

        const uint32_t sbase = smaddr + (kt % STAGES)*STAGE_BYTES;
#pragma unroll
        for (int kp = 0; kp < 2; kp++) {
            uint32_t wq[4][4];
            const uint32_t wsw = ((4*kp + w_hi) ^ x7) << 4;
#pragma unroll
            for (int ni = 0; ni < 4; ni++) {
                asm volatile("ldmatrix.sync.aligned.m8n8.x4.shared.b16 {%0,%1,%2,%3}, [%4];"
                    : "=r"(wq[ni][0]), "=r"(wq[ni][1]), "=r"(wq[ni][2]), "=r"(wq[ni][3])
                    : "r"(sbase + wRowOff[ni] + wsw));
            }
#pragma unroll
            for (int kk2 = 0; kk2 < 2; kk2++) {
                const int kk = 2*kp + kk2;
                const uint32_t asw = ((2*kk + a_hi) ^ x7) << 4;
                uint32_t af[4][4];
#pragma unroll
                for (int mi = 0; mi < 4; mi++) {
                    asm volatile("ldmatrix.sync.aligned.m8n8.x4.shared.b16 {%0,%1,%2,%3}, [%4];"
                        : "=r"(af[mi][0]), "=r"(af[mi][1]), "=r"(af[mi][2]), "=r"(af[mi][3])
                        : "r"(sbase + aRowOff[mi] + asw));
                }
#pragma unroll
                for (int mi = 0; mi < 4; mi++)
#pragma unroll
                    for (int ni = 0; ni < 4; ni++)
                        asm volatile(
                            "mma.sync.aligned.m16n8k16.row.col.f32.f16.f16.f32 "
                            "{%0,%1,%2,%3}, {%4,%5,%6,%7}, {%8,%9}, {%0,%1,%2,%3};"
                            : "+f"(acc[mi][ni][0]), "+f"(acc[mi][ni][1]),
                              "+f"(acc[mi][ni][2]), "+f"(acc[mi][ni][3])
                            : "r"(af[mi][0]), "r"(af[mi][1]), "r"(af[mi][2]), "r"(af[mi][3]),
                              "r"(wq[ni][2*kk2]), "r"(wq[ni][2*kk2+1]));
            }
        }
    }

    if (HALF_OUT) {
#pragma unroll
        for (int mi = 0; mi < 4; mi++) {
            int r0 = row0 + wm*64 + mi*16 + g;
#pragma unroll
            for (int ni = 0; ni < 4; ni++) {
                int c = col0 + wn*32 + ni*8 + 2*q;
                *(__half2*)(Ch + (size_t)r0     * Nout + c) = __floats2half2_rn(acc[mi][ni][0], acc[mi][ni][1]);
                *(__half2*)(Ch + (size_t)(r0+8) * Nout + c) = __floats2half2_rn(acc[mi][ni][2], acc[mi][ni][3]);
            }
        }
    } else {
#pragma unroll
        for (int mi = 0; mi < 4; mi++) {
            int r0 = row0 + wm*64 + mi*16 + g;
#pragma unroll
            for (int ni = 0; ni < 4; ni++) {
                int c = col0 + wn*32 + ni*8 + 2*q;
                float b0 = bias ? bias[c] : 0.f, b1 = bias ? bias[c+1] : 0.f;
                *(float2*)(Cf + (size_t)r0     * Nout + c) = make_float2(acc[mi][ni][0]+b0, acc[mi][ni][1]+b1);
                *(float2*)(Cf + (size_t)(r0+8) * Nout + c) = make_float2(acc[mi][ni][2]+b0, acc[mi][ni][3]+b1);
            }
        }
    }
#undef LOAD_STAGE_T
}

// A0 GEMM: gather, fp16 out
__global__ __launch_bounds__(256, 2)
void gemm_a0(const __half* __restrict__ A, const __half* __restrict__ W,
             __half* __restrict__ Ch, int N, const int* __restrict__ a_off)
{
    extern __shared__ uint32_t sm[];
    const uint32_t smaddr = (uint32_t)__cvta_generic_to_shared(sm);
    gemm_tile<true, true>(A, W, Ch, nullptr, blockIdx.y * BM, blockIdx.x * BN, N,
                          a_off, nullptr, smaddr, threadIdx.x);
}

// output GEMM: gather, fp32 out + bias
__global__ __launch_bounds__(256, 2)
void gemm_out(const __half* __restrict__ A, const __half* __restrict__ W,
              float* __restrict__ Cf, int N, const int* __restrict__ a_off,
              const float* __restrict__ bias)
{
    extern __shared__ uint32_t sm[];
    const uint32_t smaddr = (uint32_t)__cvta_generic_to_shared(sm);
    gemm_tile<true, false>(A, W, nullptr, Cf, blockIdx.y * BM, blockIdx.x * BN, N,
                           a_off, bias, smaddr, threadIdx.x);
}

// wavefront GEMM: 3 operand sets via z, fp16 out, gated by d_T and d_M
__global__ __launch_bounds__(256, 2)
void gemm_w(const __half* __restrict__ h0h, const __half* __restrict__ h1h,
            int t0, int t1)
{
    int tt = (blockIdx.z == 0) ? t0 : t1;
    if (tt < 0 || tt >= d_T[0]) return;
    if (blockIdx.y * BM >= d_M[tt]) return;

    const __half* A = (blockIdx.z == 1) ? h1h : h0h;
    const __half* W = (blockIdx.z == 0) ? d_Whh0h : ((blockIdx.z == 1) ? d_Whh1h : d_Wih1h);
    __half*       C = (blockIdx.z == 0) ? d_G0h : ((blockIdx.z == 1) ? d_G1h : d_A1h);

    extern __shared__ uint32_t sm[];
    const uint32_t smaddr = (uint32_t)__cvta_generic_to_shared(sm);
    gemm_tile<false, true>(A, W, C, nullptr, blockIdx.y * BM, blockIdx.x * BN, H3,
                           nullptr, nullptr, smaddr, threadIdx.x);
}

// ---------------- merged GRU pointwise ----------------
__device__ __forceinline__ float sigm(float x) { return 1.f / (1.f + __expf(-x)); }
__device__ __forceinline__ float tanh_fast(float x) { return 2.f / (1.f + __expf(-2.f*x)) - 1.f; }

__device__ __forceinline__ void ld4h(const __half* p, float* o) {
    __half2 v0 = *(const __half2*)(p);
    __half2 v1 = *(const __half2*)(p + 2);
    float2 f0 = __half22float2(v0);
    float2 f1 = __half22float2(v1);
    o[0] = f0.x; o[1] = f0.y; o[2] = f1.x; o[3] = f1.y;
}

__global__ void k_pw(const float* __restrict__ bih0, const float* __restrict__ bhh0,
                     const float* __restrict__ bih1, const float* __restrict__ bhh1,
                     const float* __restrict__ h0in, float* __restrict__ h0out,
                     __half* __restrict__ h0hout,
                     const float* __restrict__ h1in, float* __restrict__ h1out,
                     __half* __restrict__ h1hout, __half* __restrict__ yout, int k)
{
    const int T = d_T[0];
    int i4 = blockIdx.x * blockDim.x + threadIdx.x;
    if (i4 >= BH/4) return;
    int i = i4 << 2;
    int b = i >> 9, j = i & (HSZ-1);
    int base = b*H3 + j;

    const __half* Xs; const __half* Gs;
    const float* bi;  const float* bh;
    const float* hin; float* hout; __half* hhout;
    bool writeY;

    if (blockIdx.y == 0) {
        if (k >= T || b >= d_M[k]) return;
        Xs = d_A0h; Gs = d_G0h; bi = bih0; bh = bhh0;
        hin = h0in; hout = h0out; hhout = h0hout; writeY = false;
    } else {
        if (k < 1 || k-1 >= T || b >= d_M[k-1]) return;
        Xs = d_A1h; Gs = d_G1h; bi = bih1; bh = bhh1;
        hin = h1in; hout = h1out; hhout = h1hout; writeY = true;
    }

    float xr[4], xz[4], xn[4], gr[4], gz[4], gn[4];
    ld4h(Xs + base,         xr);
    ld4h(Xs + base + HSZ,   xz);
    ld4h(Xs + base + 2*HSZ, xn);
    ld4h(Gs + base,         gr);
    ld4h(Gs + base + HSZ,   gz);
    ld4h(Gs + base + 2*HSZ, gn);

    float4 h  = *(const float4*)(hin + i);
    float4 bir = *(const float4*)(bi + j);
    float4 biz = *(const float4*)(bi + j + HSZ);
    float4 bin = *(const float4*)(bi + j + 2*HSZ);
    float4 bhr = *(const float4*)(bh + j);
    float4 bhz = *(const float4*)(bh + j + HSZ);
    float4 bhn = *(const float4*)(bh + j + 2*HSZ);

    const float* ph =(const float*)&h;
    const float* pir=(const float*)&bir; const float* piz=(const float*)&biz; const float* pin=(const float*)&bin;
    const float* phr=(const float*)&bhr; const float* phz=(const float*)&bhz; const float* phn=(const float*)&bhn;

    float hn[4];
#pragma unroll
    for (int e = 0; e < 4; e++) {
        float r = sigm(xr[e]+pir[e] + gr[e]+phr[e]);
        float z = sigm(xz[e]+piz[e] + gz[e]+phz[e]);
        float n = tanh_fast(xn[e]+pin[e] + r * (gn[e]+phn[e]));
        hn[e] = (1.f - z) * n + z * ph[e];
    }

    *(float4*)(hout + i) = make_float4(hn[0], hn[1], hn[2], hn[3]);
    __half2 p0 = __floats2half2_rn(hn[0], hn[1]);
    __half2 p1 = __floats2half2_rn(hn[2], hn[3]);
    ((__half2*)(hhout + i))[0] = p0;
    ((__half2*)(hhout + i))[1] = p1;
    if (writeY) {
        ((__half2*)(yout + i))[0] = p0;
        ((__half2*)(yout + i))[1] = p1;
    }
}

// ---------------- host launch ----------------
extern "C" void kernel_launch(void* const* d_in, const int* in_sizes, int n_in,
                              void* d_out, int out_size)
{
    const float* x    = (const float*)d_in[0];
    const float* Wih0 = (const float*)d_in[1];
    const float* Whh0 = (const float*)d_in[2];
    const float* bih0 = (const float*)d_in[3];
    const float* bhh0 = (const float*)d_in[4];
    const float* Wih1 = (const float*)d_in[5];
    const float* Whh1 = (const float*)d_in[6];
    const float* bih1 = (const float*)d_in[7];
    const float* bhh1 = (const float*)d_in[8];
    const float* Wout = (const float*)d_in[9];
    const float* bout = (const float*)d_in[10];
    const int*   psi  = (const int*)d_in[11];
    float* out = (float*)d_out;

    cudaFuncSetAttribute(gemm_a0,  cudaFuncAttributeMaxDynamicSharedMemorySize, SMEM_G);
    cudaFuncSetAttribute(gemm_out, cudaFuncAttributeMaxDynamicSharedMemorySize, SMEM_G);
    cudaFuncSetAttribute(gemm_w,   cudaFuncAttributeMaxDynamicSharedMemorySize, SMEM_G);

    float *p_h0fA,*p_h0fB,*p_h1fA,*p_h1fB;
    __half *p_h0hA,*p_h0hB,*p_h1hA,*p_h1hB,*p_A0h,*p_Y1h,*p_xh,*p_Wih0h,*p_Wouth;
    int *p_rowoff,*p_xoff;
    cudaGetSymbolAddress((void**)&p_h0fA, d_h0fA);
    cudaGetSymbolAddress((void**)&p_h0fB, d_h0fB);
    cudaGetSymbolAddress((void**)&p_h1fA, d_h1fA);
    cudaGetSymbolAddress((void**)&p_h1fB, d_h1fB);
    cudaGetSymbolAddress((void**)&p_h0hA, d_h0hA);
    cudaGetSymbolAddress((void**)&p_h0hB, d_h0hB);
    cudaGetSymbolAddress((void**)&p_h1hA, d_h1hA);
    cudaGetSymbolAddress((void**)&p_h1hB, d_h1hB);
    cudaGetSymbolAddress((void**)&p_A0h,  d_A0h);
    cudaGetSymbolAddress((void**)&p_Y1h,  d_Y1h);
    cudaGetSymbolAddress((void**)&p_xh,   d_xh);
    cudaGetSymbolAddress((void**)&p_Wih0h,d_Wih0h);
    cudaGetSymbolAddress((void**)&p_Wouth,d_Wouth);
    cudaGetSymbolAddress((void**)&p_rowoff, d_rowoff);
    cudaGetSymbolAddress((void**)&p_xoff,   d_xoff);

    const int PWI = (BH + 255) / 256;
    const int PW4 = (BH/4 + 255) / 256;

    k_init_first<<<PWI, 256>>>(psi);
    k_count<<<(NSZ + 255) / 256, 256>>>(psi);
    k_hist<<<BSZ/256, 256>>>();
    k_start<<<1, 32>>>();
    k_scatter<<<BSZ/256, 256>>>();
    k_rank<<<(NSZ + 255) / 256, 256>>>(psi);
    k_convAll<<<(BSZ*INSZ/4 + 255)/256, 256>>>(x, Wih0, Whh0, Wih1, Whh1, Wout);

    // A0 (permuted rows via gather) = x[perm] . Wih0^T  (fp16 out; biases in pw)
    gemm_a0<<<dim3(H3/BN, BSZ/BM), 256, SMEM_G>>>(p_xh, p_Wih0h, p_A0h, H3, p_xoff);

    float  *h0f_in = p_h0fA, *h0f_out = p_h0fB;
    float  *h1f_in = p_h1fA, *h1f_out = p_h1fB;
    __half *h0h_in = p_h0hA, *h0h_out = p_h0hB;
    __half *h1h_in = p_h1hA, *h1h_out = p_h1hB;

    // wavefront: iteration k = layer0 step k + layer1 step k-1, active-prefix gated
    for (int k = 0; k <= T_MAX; k++) {
        gemm_w<<<dim3(H3/BN, BSZ/BM, 3), 256, SMEM_G>>>(h0h_in, h1h_in, k, k-1);

        __half* yptr = p_Y1h + (size_t)(k > 0 ? k-1 : 0) * BH;
        k_pw<<<dim3(PW4, 2), 256>>>(bih0, bhh0, bih1, bhh1,
                                    h0f_in, h0f_out, h0h_out,
                                    h1f_in, h1f_out, h1h_out, yptr, k);

        float* tf; __half* th;
        tf = h0f_in; h0f_in = h0f_out; h0f_out = tf;
        tf = h1f_in; h1f_in = h1f_out; h1f_out = tf;
        th = h0h_in; h0h_in = h0h_out; h0h_out = th;
        th = h1h_in; h1h_in = h1h_out; h1h_out = th;
    }

    // gathered output GEMM: out[N, OUT] = Y1h[rowoff[j]] . Wout^T + bout
    gemm_out<<<dim3(OUTSZ/BN, NSZ/BM), 256, SMEM_G>>>(p_Y1h, p_Wouth, out, OUTSZ, p_rowoff, bout);

    (void)in_sizes; (void)n_in; (void)out_size;
}

// round 15
// speedup vs baseline: 1.7158x; 1.0759x over previous
#include <cuda_runtime.h>
#include <cuda_fp16.h>
#include <math.h>
#include <stdint.h>

#define BSZ   2048
#define INSZ  512
#define HSZ   512
#define OUTSZ 256
#define NSZ   32768
#define H3    (3*HSZ)
#define T_MAX 40
#define BH    (BSZ*HSZ)

#define BM 128
#define BN 128
#define STAGE_BYTES (2*BM*128)
#define STAGES 3
#define SMEM_G (STAGES*STAGE_BYTES)      // 98304
#define KCONST 512
#define KT8    (KCONST/64)               // 8

// ---- PDL intrinsics ----
__device__ __forceinline__ void pdl_wait()    { asm volatile("griddepcontrol.wait;" ::: "memory"); }
__device__ __forceinline__ void pdl_trigger() { asm volatile("griddepcontrol.launch_dependents;"); }

// ---------------- device scratch ----------------
__device__ float  d_h0fA[BH], d_h0fB[BH], d_h1fA[BH], d_h1fB[BH];
__device__ __half d_h0hA[BH], d_h0hB[BH], d_h1hA[BH], d_h1hB[BH];
__device__ __half d_A0h[BSZ*H3];
__device__ __half d_G0h[BSZ*H3];
__device__ __half d_G1h[BSZ*H3];
__device__ __half d_A1h[BSZ*H3];
__device__ __half d_Y1h[(size_t)T_MAX*BH];
__device__ __half d_xh   [BSZ*INSZ];
__device__ __half d_Wih0h[H3*INSZ];
__device__ __half d_Whh0h[H3*HSZ];
__device__ __half d_Wih1h[H3*HSZ];
__device__ __half d_Whh1h[H3*HSZ];
__device__ __half d_Wouth[OUTSZ*HSZ];
__device__ int    d_first[BSZ];
__device__ int    d_cnt[BSZ];
__device__ int    d_pos[BSZ];
__device__ int    d_xoff[BSZ];
__device__ int    d_rowoff[NSZ];
__device__ int    d_hist[64];
__device__ int    d_off[64];
__device__ int    d_start[64];
__device__ int    d_M[T_MAX+1];
__device__ int    d_T[1];

// ---------------- setup (counting sort) ----------------
__global__ void k_init_first(const int* __restrict__ psi) {
    int i = blockIdx.x * blockDim.x + threadIdx.x;
    if (i == 0) d_T[0] = 0;
    if (i < 64) { d_hist[i] = 0; d_off[i] = 0; }
    if (i < BSZ) d_cnt[i] = 0;
    if (i < BH) {
        d_h0fA[i]=0.f; d_h0fB[i]=0.f; d_h1fA[i]=0.f; d_h1fB[i]=0.f;
        __half z = __float2half(0.f);
        d_h0hA[i]=z; d_h0hB[i]=z; d_h1hA[i]=z; d_h1hB[i]=z;
    }
    if (i < NSZ) {
        if (i == 0 || psi[i] != psi[i-1]) d_first[psi[i]] = i;
    }
}

__global__ void k_count(const int* __restrict__ psi) {
    int j = blockIdx.x * blockDim.x + threadIdx.x;
    if (j < NSZ) atomicAdd(&d_cnt[psi[j]], 1);
}

__global__ void k_hist() {
    int i = blockIdx.x * blockDim.x + threadIdx.x;
    if (i >= BSZ) return;
    int c = d_cnt[i] < 63 ? d_cnt[i] : 63;
    atomicAdd(&d_hist[c], 1);
    atomicMax(&d_T[0], d_cnt[i]);
}

__global__ void k_start() {
    if (threadIdx.x == 0) {
        int run = 0;
        for (int c = 63; c >= 0; c--) {
            d_start[c] = run;
            run += d_hist[c];
        }
        for (int t = 0; t <= T_MAX; t++)
            d_M[t] = (t < 64) ? d_start[t] : 0;
    }
}

__global__ void k_scatter() {
    int i = blockIdx.x * blockDim.x + threadIdx.x;
    if (i >= BSZ) return;
    int c = d_cnt[i] < 63 ? d_cnt[i] : 63;
    int pos = d_start[c] + atomicAdd(&d_off[c], 1);
    d_pos[i] = pos;
    d_xoff[pos] = i * INSZ;
}

__global__ void k_rank(const int* __restrict__ psi) {
    int j = blockIdx.x * blockDim.x + threadIdx.x;
    if (j >= NSZ) return;
    int v = psi[j];
    int r = j - d_first[v];
    d_rowoff[j] = r * BH + d_pos[v] * HSZ;
}

__device__ __forceinline__ void conv4(const float* src, __half* dst, int i) {
    float4 v = *(const float4*)(src + i);
    ((__half2*)(dst + i))[0] = __floats2half2_rn(v.x, v.y);
    ((__half2*)(dst + i))[1] = __floats2half2_rn(v.z, v.w);
}

__global__ void k_convAll(const float* __restrict__ x,  const float* __restrict__ wih0,
                          const float* __restrict__ whh0, const float* __restrict__ wih1,
                          const float* __restrict__ whh1, const float* __restrict__ wout) {
    int i = (blockIdx.x * blockDim.x + threadIdx.x) << 2;
    if (i < BSZ*INSZ)  conv4(x,    d_xh,    i);
    if (i < H3*INSZ)   conv4(wih0, d_Wih0h, i);
    if (i < H3*HSZ) {
        conv4(whh0, d_Whh0h, i);
        conv4(wih1, d_Wih1h, i);
        conv4(whh1, d_Whh1h, i);
    }
    if (i < OUTSZ*HSZ) conv4(wout, d_Wouth, i);
}

// ---------------- GEMM tile: 128x128, 256 thr, 3-stage, K=512 compile-time ----------------
template<bool GATHER, bool HALF_OUT>
__device__ __forceinline__ void gemm_tile(
    const __half* __restrict__ A, const __half* __restrict__ W,
    __half* __restrict__ Ch, float* __restrict__ Cf,
    int row0, int col0, int Nout,
    const int* __restrict__ a_off, const float* __restrict__ bias,
    uint32_t smaddr, int tid)
{
    const int lane = tid & 31;
    const int warp = tid >> 5;
    const int wm   = warp >> 2;
    const int wn   = warp & 3;
    const int g    = lane >> 2;
    const int q    = lane & 3;

    const int lm   = tid >> 1;
    const int lkg0 = (tid & 1) * 4;

    const __half* agp;
    if (GATHER) agp = A + a_off[row0 + lm];
    else        agp = A + (size_t)(row0 + lm) * KCONST;
    const __half* wgp = W + (size_t)(col0 + lm) * KCONST;

    uint32_t soffB[4];
#pragma unroll
    for (int j = 0; j < 4; j++)
        soffB[j] = (uint32_t)(lm * 128 + (((lkg0 + j) ^ (lm & 7)) << 4));

#define LOAD_STAGE_T(st, kt) do {                                            \
        uint32_t dA = smaddr + (st)*STAGE_BYTES;                             \
        uint32_t dW = dA + BM*128;                                           \
        const __half* ga = agp + (kt)*64;                                    \
        const __half* gw = wgp + (kt)*64;                                    \
        _Pragma("unroll")                                                    \
        for (int j = 0; j < 4; j++) {                                        \
            asm volatile("cp.async.cg.shared.global [%0], [%1], 16;"         \
                         :: "r"(dA + soffB[j]), "l"(ga + (lkg0 + j)*8));     \
            asm volatile("cp.async.cg.shared.global [%0], [%1], 16;"         \
                         :: "r"(dW + soffB[j]), "l"(gw + (lkg0 + j)*8));     \
        }                                                                    \
    } while (0)

    float acc[4][4][4];
#pragma unroll
    for (int a = 0; a < 4; a++)
#pragma unroll
        for (int b = 0; b < 4; b++)
#pragma unroll
            for (int c = 0; c < 4; c++) acc[a][b][c] = 0.f;

#pragma unroll
    for (int s = 0; s < STAGES-1; s++) {
        LOAD_STAGE_T(s, s);
        asm volatile("cp.async.commit_group;" ::: "memory");
    }

    const uint32_t a_row15 = lane & 15;
    const uint32_t a_hi    = lane >> 4;
    const uint32_t x7      = lane & 7;
    const uint32_t w_hi    = lane >> 3;

    uint32_t aRowOff[4], wRowOff[4];
#pragma unroll
    for (int mi = 0; mi < 4; mi++)
        aRowOff[mi] = (uint32_t)((wm*64 + mi*16 + a_row15) * 128);
#pragma unroll
    for (int ni = 0; ni < 4; ni++)
        wRowOff[ni] = (uint32_t)((BM*128) + (wn*32 + ni*8 + x7) * 128);

#pragma unroll
    for (int kt = 0; kt < KT8; kt++) {
        asm volatile("cp.async.wait_group %0;" :: "n"(STAGES-2) : "memory");
        __syncthreads();
        if (kt + STAGES - 1 < KT8) LOAD_STAGE_T((kt + STAGES - 1) % STAGES, kt + STAGES - 1);
        asm volatile("cp.async.commit_group;" ::: "memory");

        const uint32_t sbase = smaddr + (kt % STAGES)*STAGE_BYTES;
#pragma unroll
        for (int kp = 0; kp < 2; kp++) {
            uint32_t wq[4][4];
            const uint32_t wsw = ((4*kp + w_hi) ^ x7) << 4;
#pragma unroll
            for (int ni = 0; ni < 4; ni++) {
                asm volatile("ldmatrix.sync.aligned.m8n8.x4.shared.b16 {%0,%1,%2,%3}, [%4];"
                    : "=r"(wq[ni][0]), "=r"(wq[ni][1]), "=r"(wq[ni][2]), "=r"(wq[ni][3])
                    : "r"(sbase + wRowOff[ni] + wsw));
            }
#pragma unroll
            for (int kk2 = 0; kk2 < 2; kk2++) {
                const int kk = 2*kp + kk2;
                const uint32_t asw = ((2*kk + a_hi) ^ x7) << 4;
                uint32_t af[4][4];
#pragma unroll
                for (int mi = 0; mi < 4; mi++) {
                    asm volatile("ldmatrix.sync.aligned.m8n8.x4.shared.b16 {%0,%1,%2,%3}, [%4];"
                        : "=r"(af[mi][0]), "=r"(af[mi][1]), "=r"(af[mi][2]), "=r"(af[mi][3])
                        : "r"(sbase + aRowOff[mi] + asw));
                }
#pragma unroll
                for (int mi = 0; mi < 4; mi++)
#pragma unroll
                    for (int ni = 0; ni < 4; ni++)
                        asm volatile(
                            "mma.sync.aligned.m16n8k16.row.col.f32.f16.f16.f32 "
                            "{%0,%1,%2,%3}, {%4,%5,%6,%7}, {%8,%9}, {%0,%1,%2,%3};"
                            : "+f"(acc[mi][ni][0]), "+f"(acc[mi][ni][1]),
                              "+f"(acc[mi][ni][2]), "+f"(acc[mi][ni][3])
                            : "r"(af[mi][0]), "r"(af[mi][1]), "r"(af[mi][2]), "r"(af[mi][3]),
                              "r"(wq[ni][2*kk2]), "r"(wq[ni][2*kk2+1]));
            }
        }
    }

    if (HALF_OUT) {
#pragma unroll
        for (int mi = 0; mi < 4; mi++) {
            int r0 = row0 + wm*64 + mi*16 + g;
#pragma unroll
            for (int ni = 0; ni < 4; ni++) {
                int c = col0 + wn*32 + ni*8 + 2*q;
                *(__half2*)(Ch + (size_t)r0     * Nout + c) = __floats2half2_rn(acc[mi][ni][0], acc[mi][ni][1]);
                *(__half2*)(Ch + (size_t)(r0+8) * Nout + c) = __floats2half2_rn(acc[mi][ni][2], acc[mi][ni][3]);
            }
        }
    } else {
#pragma unroll
        for (int mi = 0; mi < 4; mi++) {
            int r0 = row0 + wm*64 + mi*16 + g;
#pragma unroll
            for (int ni = 0; ni < 4; ni++) {
                int c = col0 + wn*32 + ni*8 + 2*q;
                float b0 = bias ? bias[c] : 0.f, b1 = bias ? bias[c+1] : 0.f;
                *(float2*)(Cf + (size_t)r0     * Nout + c) = make_float2(acc[mi][ni][0]+b0, acc[mi][ni][1]+b1);
                *(float2*)(Cf + (size_t)(r0+8) * Nout + c) = make_float2(acc[mi][ni][2]+b0, acc[mi][ni][3]+b1);
            }
        }
    }
#undef LOAD_STAGE_T
}

// A0 GEMM: gather, fp16 out (not PDL-dependent)
__global__ __launch_bounds__(256, 2)
void gemm_a0(const __half* __restrict__ A, const __half* __restrict__ W,
             __half* __restrict__ Ch, int N, const int* __restrict__ a_off)
{
    extern __shared__ uint32_t sm[];
    const uint32_t smaddr = (uint32_t)__cvta_generic_to_shared(sm);
    gemm_tile<true, true>(A, W, Ch, nullptr, blockIdx.y * BM, blockIdx.x * BN, N,
                          a_off, nullptr, smaddr, threadIdx.x);
    pdl_trigger();   // allow first gemm_w to pre-launch
}

// output GEMM: gather, fp32 out + bias (PDL-dependent on last pw)
__global__ __launch_bounds__(256, 2)
void gemm_out(const __half* __restrict__ A, const __half* __restrict__ W,
              float* __restrict__ Cf, int N, const int* __restrict__ a_off,
              const float* __restrict__ bias)
{
    extern __shared__ uint32_t sm[];
    const uint32_t smaddr = (uint32_t)__cvta_generic_to_shared(sm);
    pdl_wait();
    gemm_tile<true, false>(A, W, nullptr, Cf, blockIdx.y * BM, blockIdx.x * BN, N,
                           a_off, bias, smaddr, threadIdx.x);
}

// wavefront GEMM: 3 operand sets via z, fp16 out, gated by d_T and d_M
__global__ __launch_bounds__(256, 2)
void gemm_w(const __half* __restrict__ h0h, const __half* __restrict__ h1h,
            int t0, int t1)
{
    // d_T / d_M are stable after setup: safe to read before pdl_wait
    int tt = (blockIdx.z == 0) ? t0 : t1;
    if (tt < 0 || tt >= d_T[0]) return;
    if (blockIdx.y * BM >= d_M[tt]) return;

    const __half* A = (blockIdx.z == 1) ? h1h : h0h;
    const __half* W = (blockIdx.z == 0) ? d_Whh0h : ((blockIdx.z == 1) ? d_Whh1h : d_Wih1h);
    __half*       C = (blockIdx.z == 0) ? d_G0h : ((blockIdx.z == 1) ? d_G1h : d_A1h);

    extern __shared__ uint32_t sm[];
    const uint32_t smaddr = (uint32_t)__cvta_generic_to_shared(sm);

    pdl_wait();   // h state from previous pw must be complete
    gemm_tile<false, true>(A, W, C, nullptr, blockIdx.y * BM, blockIdx.x * BN, H3,
                           nullptr, nullptr, smaddr, threadIdx.x);
    pdl_trigger();
}

// ---------------- merged GRU pointwise ----------------
__device__ __forceinline__ float sigm(float x) { return 1.f / (1.f + __expf(-x)); }
__device__ __forceinline__ float tanh_fast(float x) { return 2.f / (1.f + __expf(-2.f*x)) - 1.f; }

__device__ __forceinline__ void ld4h(const __half* p, float* o) {
    __half2 v0 = *(const __half2*)(p);
    __half2 v1 = *(const __half2*)(p + 2);
    float2 f0 = __half22float2(v0);
    float2 f1 = __half22float2(v1);
    o[0] = f0.x; o[1] = f0.y; o[2] = f1.x; o[3] = f1.y;
}

__global__ void k_pw(const float* __restrict__ bih0, const float* __restrict__ bhh0,
                     const float* __restrict__ bih1, const float* __restrict__ bhh1,
                     const float* __restrict__ h0in, float* __restrict__ h0out,
                     __half* __restrict__ h0hout,
                     const float* __restrict__ h1in, float* __restrict__ h1out,
                     __half* __restrict__ h1hout, __half* __restrict__ yout, int k)
{
    const int T = d_T[0];
    int i4 = blockIdx.x * blockDim.x + threadIdx.x;
    if (i4 >= BH/4) return;
    int i = i4 << 2;
    int b = i >> 9, j = i & (HSZ-1);
    int base = b*H3 + j;

    const __half* Xs; const __half* Gs;
    const float* bi;  const float* bh;
    const float* hin; float* hout; __half* hhout;
    bool writeY;

    if (blockIdx.y == 0) {
        if (k >= T || b >= d_M[k]) return;
        Xs = d_A0h; Gs = d_G0h; bi = bih0; bh = bhh0;
        hin = h0in; hout = h0out; hhout = h0hout; writeY = false;
    } else {
        if (k < 1 || k-1 >= T || b >= d_M[k-1]) return;
        Xs = d_A1h; Gs = d_G1h; bi = bih1; bh = bhh1;
        hin = h1in; hout = h1out; hhout = h1hout; writeY = true;
    }

    // biases and h_in are stable w.r.t. the immediately preceding gemm_w: prefetch
    float4 h  = *(const float4*)(hin + i);
    float4 bir = *(const float4*)(bi + j);
    float4 biz = *(const float4*)(bi + j + HSZ);
    float4 bin = *(const float4*)(bi + j + 2*HSZ);
    float4 bhr = *(const float4*)(bh + j);
    float4 bhz = *(const float4*)(bh + j + HSZ);
    float4 bhn = *(const float4*)(bh + j + 2*HSZ);

    pdl_wait();   // gates from gemm_w must be complete

    float xr[4], xz[4], xn[4], gr[4], gz[4], gn[4];
    ld4h(Xs + base,         xr);
    ld4h(Xs + base + HSZ,   xz);
    ld4h(Xs + base + 2*HSZ, xn);
    ld4h(Gs + base,         gr);
    ld4h(Gs + base + HSZ,   gz);
    ld4h(Gs + base + 2*HSZ, gn);

    const float* ph =(const float*)&h;
    const float* pir=(const float*)&bir; const float* piz=(const float*)&biz; const float* pin=(const float*)&bin;
    const float* phr=(const float*)&bhr; const float* phz=(const float*)&bhz; const float* phn=(const float*)&bhn;

    float hn[4];
#pragma unroll
    for (int e = 0; e < 4; e++) {
        float r = sigm(xr[e]+pir[e] + gr[e]+phr[e]);
        float z = sigm(xz[e]+piz[e] + gz[e]+phz[e]);
        float n = tanh_fast(xn[e]+pin[e] + r * (gn[e]+phn[e]));
        hn[e] = (1.f - z) * n + z * ph[e];
    }

    *(float4*)(hout + i) = make_float4(hn[0], hn[1], hn[2], hn[3]);
    __half2 p0 = __floats2half2_rn(hn[0], hn[1]);
    __half2 p1 = __floats2half2_rn(hn[2], hn[3]);
    ((__half2*)(hhout + i))[0] = p0;
    ((__half2*)(hhout + i))[1] = p1;
    if (writeY) {
        ((__half2*)(yout + i))[0] = p0;
        ((__half2*)(yout + i))[1] = p1;
    }
    pdl_trigger();
}

// ---------------- host launch ----------------
extern "C" void kernel_launch(void* const* d_in, const int* in_sizes, int n_in,
                              void* d_out, int out_size)
{
    const float* x    = (const float*)d_in[0];
    const float* Wih0 = (const float*)d_in[1];
    const float* Whh0 = (const float*)d_in[2];
    const float* bih0 = (const float*)d_in[3];
    const float* bhh0 = (const float*)d_in[4];
    const float* Wih1 = (const float*)d_in[5];
    const float* Whh1 = (const float*)d_in[6];
    const float* bih1 = (const float*)d_in[7];
    const float* bhh1 = (const float*)d_in[8];
    const float* Wout = (const float*)d_in[9];
    const float* bout = (const float*)d_in[10];
    const int*   psi  = (const int*)d_in[11];
    float* out = (float*)d_out;

    cudaFuncSetAttribute(gemm_a0,  cudaFuncAttributeMaxDynamicSharedMemorySize, SMEM_G);
    cudaFuncSetAttribute(gemm_out, cudaFuncAttributeMaxDynamicSharedMemorySize, SMEM_G);
    cudaFuncSetAttribute(gemm_w,   cudaFuncAttributeMaxDynamicSharedMemorySize, SMEM_G);

    float *p_h0fA,*p_h0fB,*p_h1fA,*p_h1fB;
    __half *p_h0hA,*p_h0hB,*p_h1hA,*p_h1hB,*p_A0h,*p_Y1h,*p_xh,*p_Wih0h,*p_Wouth;
    int *p_rowoff,*p_xoff;
    cudaGetSymbolAddress((void**)&p_h0fA, d_h0fA);
    cudaGetSymbolAddress((void**)&p_h0fB, d_h0fB);
    cudaGetSymbolAddress((void**)&p_h1fA, d_h1fA);
    cudaGetSymbolAddress((void**)&p_h1fB, d_h1fB);
    cudaGetSymbolAddress((void**)&p_h0hA, d_h0hA);
    cudaGetSymbolAddress((void**)&p_h0hB, d_h0hB);
    cudaGetSymbolAddress((void**)&p_h1hA, d_h1hA);
    cudaGetSymbolAddress((void**)&p_h1hB, d_h1hB);
    cudaGetSymbolAddress((void**)&p_A0h,  d_A0h);
    cudaGetSymbolAddress((void**)&p_Y1h,  d_Y1h);
    cudaGetSymbolAddress((void**)&p_xh,   d_xh);
    cudaGetSymbolAddress((void**)&p_Wih0h,d_Wih0h);
    cudaGetSymbolAddress((void**)&p_Wouth,d_Wouth);
    cudaGetSymbolAddress((void**)&p_rowoff, d_rowoff);
    cudaGetSymbolAddress((void**)&p_xoff,   d_xoff);

    const int PWI = (BH + 255) / 256;
    const int PW4 = (BH/4 + 255) / 256;

    k_init_first<<<PWI, 256>>>(psi);
    k_count<<<(NSZ + 255) / 256, 256>>>(psi);
    k_hist<<<BSZ/256, 256>>>();
    k_start<<<1, 32>>>();
    k_scatter<<<BSZ/256, 256>>>();
    k_rank<<<(NSZ + 255) / 256, 256>>>(psi);
    k_convAll<<<(BSZ*INSZ/4 + 255)/256, 256>>>(x, Wih0, Whh0, Wih1, Whh1, Wout);

    // A0 (permuted rows via gather) = x[perm] . Wih0^T  (fp16 out; biases in pw)
    gemm_a0<<<dim3(H3/BN, BSZ/BM), 256, SMEM_G>>>(p_xh, p_Wih0h, p_A0h, H3, p_xoff);

    // PDL launch attribute (shared)
    cudaLaunchAttribute pdlAttr[1];
    pdlAttr[0].id = cudaLaunchAttributeProgrammaticStreamSerialization;
    pdlAttr[0].val.programmaticStreamSerializationAllowed = 1;

    float  *h0f_in = p_h0fA, *h0f_out = p_h0fB;
    float  *h1f_in = p_h1fA, *h1f_out = p_h1fB;
    __half *h0h_in = p_h0hA, *h0h_out = p_h0hB;
    __half *h1h_in = p_h1hA, *h1h_out = p_h1hB;

    for (int k = 0; k <= T_MAX; k++) {
        {
            cudaLaunchConfig_t cfg = {};
            cfg.gridDim = dim3(H3/BN, BSZ/BM, 3);
            cfg.blockDim = dim3(256, 1, 1);
            cfg.dynamicSmemBytes = SMEM_G;
            cfg.attrs = pdlAttr;
            cfg.numAttrs = 1;
            cudaLaunchKernelEx(&cfg, gemm_w,
                               (const __half*)h0h_in, (const __half*)h1h_in, k, k-1);
        }
        {
            __half* yptr = p_Y1h + (size_t)(k > 0 ? k-1 : 0) * BH;
            cudaLaunchConfig_t cfg = {};
            cfg.gridDim = dim3(PW4, 2, 1);
            cfg.blockDim = dim3(256, 1, 1);
            cfg.dynamicSmemBytes = 0;
            cfg.attrs = pdlAttr;
            cfg.numAttrs = 1;
            cudaLaunchKernelEx(&cfg, k_pw,
                               bih0, bhh0, bih1, bhh1,
                               (const float*)h0f_in, h0f_out, h0h_out,
                               (const float*)h1f_in, h1f_out, h1h_out, yptr, k);
        }

        float* tf; __half* th;
        tf = h0f_in; h0f_in = h0f_out; h0f_out = tf;
        tf = h1f_in; h1f_in = h1f_out; h1f_out = tf;
        th = h0h_in; h0h_in = h0h_out; h0h_out = th;
        th = h1h_in; h1h_in = h1h_out; h1h_out = th;
    }

    // gathered output GEMM: out[N, OUT] = Y1h[rowoff[j]] . Wout^T + bout
    {
        cudaLaunchConfig_t cfg = {};
        cfg.gridDim = dim3(OUTSZ/BN, NSZ/BM, 1);
        cfg.blockDim = dim3(256, 1, 1);
        cfg.dynamicSmemBytes = SMEM_G;
        cfg.attrs = pdlAttr;
        cfg.numAttrs = 1;
        cudaLaunchKernelEx(&cfg, gemm_out,
                           (const __half*)p_Y1h, (const __half*)p_Wouth, out,
                           OUTSZ, (const int*)p_rowoff, bout);
    }

    (void)in_sizes; (void)n_in; (void)out_size;
}